// round 4
// baseline (speedup 1.0000x reference)
#include <cuda_runtime.h>
#include <math.h>
#include <stdint.h>

// Problem constants
#define BB 2
#define SS 2048
#define DD 1024
#define HH 16
#define DHH 64
#define MM (BB*SS)          // 4096 rows
#define LAMBDA_INIT 0.8f
#define GN_EPS 1e-5f

// Scratch (device globals; no allocation allowed)
__device__ float g_Q[MM*DD];
__device__ float g_K[MM*DD];
__device__ float g_V[MM*DD];
__device__ float g_AO[MM*DD];   // attention output [B,S,H,DH]
__device__ float g_lam[HH];
__device__ float g_mean[BB*HH];
__device__ float g_rstd[BB*HH];

// ---------------------------------------------------------------------------
// helpers
// ---------------------------------------------------------------------------
__device__ __forceinline__ float to_tf32(float x) {
    unsigned u;
    asm("cvt.rna.tf32.f32 %0, %1;" : "=r"(u) : "f"(x));
    return __uint_as_float(u);
}
__device__ __forceinline__ int swz(int l) { return l ^ (l >> 3); }

__device__ __forceinline__ void mma_tf32(float* c, const float* a, const float* b) {
    const unsigned* A = reinterpret_cast<const unsigned*>(a);
    const unsigned* B = reinterpret_cast<const unsigned*>(b);
    asm volatile(
        "mma.sync.aligned.m16n8k8.row.col.f32.tf32.tf32.f32 "
        "{%0,%1,%2,%3}, {%4,%5,%6,%7}, {%8,%9}, {%0,%1,%2,%3};\n"
        : "+f"(c[0]), "+f"(c[1]), "+f"(c[2]), "+f"(c[3])
        : "r"(A[0]), "r"(A[1]), "r"(A[2]), "r"(A[3]),
          "r"(B[0]), "r"(B[1]));
}

// ---------------------------------------------------------------------------
// lambda[h] = exp(<lq1,lk1>) - exp(<lq2,lk2>) + 0.8  (one warp/head)
// ---------------------------------------------------------------------------
__global__ void lambda_kernel(const float* __restrict__ lq1, const float* __restrict__ lk1,
                              const float* __restrict__ lq2, const float* __restrict__ lk2,
                              float* __restrict__ lam) {
    int h = threadIdx.x >> 5;
    int lane = threadIdx.x & 31;
    const float* a1 = lq1 + h * DHH;
    const float* b1 = lk1 + h * DHH;
    const float* a2 = lq2 + h * DHH;
    const float* b2 = lk2 + h * DHH;
    float s1 = a1[lane] * b1[lane] + a1[lane + 32] * b1[lane + 32];
    float s2 = a2[lane] * b2[lane] + a2[lane + 32] * b2[lane + 32];
    #pragma unroll
    for (int off = 16; off > 0; off >>= 1) {
        s1 += __shfl_xor_sync(0xffffffffu, s1, off);
        s2 += __shfl_xor_sync(0xffffffffu, s2, off);
    }
    if (lane == 0) lam[h] = expf(s1) - expf(s2) + LAMBDA_INIT;
}

// ---------------------------------------------------------------------------
// tf32 MMA GEMM with fragment-layout smem.
// C[M,1024] = A[M,1024] @ B[1024,1024] + bias   (B in original [K][N] layout)
// BM=128 BN=128 BK=16, 256 threads = 8 warps (2x4), warp tile 64x32.
// Fragment smem: A-blocks (16 rows x 8 k) = 32 lanes x 4 floats, padded to 132.
//                B-blocks (8 cols x 8 k)  = 32 lanes x 2 floats, padded to 68.
// FUSE=1: A -> ((A - mean[b,h]) * rstd[b,h]) * gnw[k] + gnb[k]
// ---------------------------------------------------------------------------
#define ABLK 132
#define BBLK 68

template<int FUSE>
__global__ __launch_bounds__(256) void gemm_frag(
    const float* __restrict__ A, const float* __restrict__ B,
    const float* __restrict__ bias, float* __restrict__ C,
    const float* __restrict__ mean, const float* __restrict__ rstd,
    const float* __restrict__ gnw, const float* __restrict__ gnb)
{
    __shared__ float Af[2][16 * ABLK];   // (gmt 0..7, kt 0..1)
    __shared__ float Bf[2][32 * BBLK];   // (gnt 0..15, kt 0..1)

    const int tid  = threadIdx.x;
    const int warp = tid >> 5;
    const int lane = tid & 31;
    const int g    = lane >> 2;
    const int tig  = lane & 3;
    const int wm   = warp >> 2;    // 0..1
    const int wn   = warp & 3;     // 0..3
    const int bm   = blockIdx.y * 128;
    const int bn   = blockIdx.x * 128;
    const int sl4  = swz(lane) * 4;
    const int sl2  = swz(lane) * 2;

    // fill index precompute (2 float4 per thread per operand)
    int ar[2], adg[2], bkr[2], bc[2];
    #pragma unroll
    for (int i = 0; i < 2; i++) {
        int idx = tid + i * 256;
        ar[i]  = idx >> 2;           // 0..127
        adg[i] = (idx & 3) << 2;     // 0,4,8,12
        bkr[i] = idx >> 5;           // 0..15
        bc[i]  = (idx & 31) << 2;    // 0..124
    }

    float c[4][4][4];
    #pragma unroll
    for (int mt = 0; mt < 4; mt++)
        #pragma unroll
        for (int nt = 0; nt < 4; nt++)
            #pragma unroll
            for (int r = 0; r < 4; r++) c[mt][nt][r] = 0.f;

    float4 fa[2], fb[2];
    const int NT = DD / 16;

    auto do_fetch = [&](int kt16) {
        #pragma unroll
        for (int i = 0; i < 2; i++) {
            fa[i] = *(const float4*)(A + (size_t)(bm + ar[i]) * DD + kt16 + adg[i]);
            if (FUSE) {
                int k  = kt16 + adg[i];
                int bi = (bm + ar[i]) >> 11;
                float mu = mean[bi * HH + (k >> 6)];
                float rs = rstd[bi * HH + (k >> 6)];
                float4 w  = *(const float4*)(gnw + k);
                float4 gb = *(const float4*)(gnb + k);
                fa[i].x = (fa[i].x - mu) * rs * w.x + gb.x;
                fa[i].y = (fa[i].y - mu) * rs * w.y + gb.y;
                fa[i].z = (fa[i].z - mu) * rs * w.z + gb.z;
                fa[i].w = (fa[i].w - mu) * rs * w.w + gb.w;
            }
            fb[i] = *(const float4*)(B + (size_t)(kt16 + bkr[i]) * DD + bn + bc[i]);
        }
    };
    auto do_store = [&](int buf) {
        #pragma unroll
        for (int i = 0; i < 2; i++) {
            // A fragment scatter
            {
                int gmt = ar[i] >> 4, rr = ar[i] & 15;
                int ga = rr & 7, hi = rr >> 3;
                int kt = adg[i] >> 3, half = (adg[i] >> 2) & 1;
                float* blk = Af[buf] + (gmt * 2 + kt) * ABLK;
                int reg = hi + 2 * half;
                float vv[4] = {fa[i].x, fa[i].y, fa[i].z, fa[i].w};
                #pragma unroll
                for (int j = 0; j < 4; j++)
                    blk[swz(4 * ga + j) * 4 + reg] = to_tf32(vv[j]);
            }
            // B fragment scatter
            {
                int kt = bkr[i] >> 3, half = (bkr[i] >> 2) & 1, tb = bkr[i] & 3;
                float vv[4] = {fb[i].x, fb[i].y, fb[i].z, fb[i].w};
                #pragma unroll
                for (int j = 0; j < 4; j++) {
                    int cc = bc[i] + j;
                    float* blk = Bf[buf] + ((cc >> 3) * 2 + kt) * BBLK;
                    blk[swz(4 * (cc & 7) + tb) * 2 + half] = to_tf32(vv[j]);
                }
            }
        }
    };

    do_fetch(0);
    do_store(0);
    __syncthreads();

    for (int t = 0; t < NT; t++) {
        int buf = t & 1;
        if (t + 1 < NT) do_fetch((t + 1) * 16);

        #pragma unroll
        for (int kp = 0; kp < 2; kp++) {
            float a[4][4], b[4][2];
            #pragma unroll
            for (int mt = 0; mt < 4; mt++)
                *(float4*)a[mt] = *(const float4*)(Af[buf] + ((wm * 4 + mt) * 2 + kp) * ABLK + sl4);
            #pragma unroll
            for (int nt = 0; nt < 4; nt++)
                *(float2*)b[nt] = *(const float2*)(Bf[buf] + ((wn * 4 + nt) * 2 + kp) * BBLK + sl2);
            #pragma unroll
            for (int mt = 0; mt < 4; mt++)
                #pragma unroll
                for (int nt = 0; nt < 4; nt++)
                    mma_tf32(c[mt][nt], a[mt], b[nt]);
        }

        if (t + 1 < NT) do_store(buf ^ 1);
        __syncthreads();
    }

    // epilogue + bias
    #pragma unroll
    for (int mt = 0; mt < 4; mt++) {
        int row = bm + wm * 64 + mt * 16 + g;
        #pragma unroll
        for (int nt = 0; nt < 4; nt++) {
            int col = bn + wn * 32 + nt * 8 + 2 * tig;
            float2 bb = *(const float2*)(bias + col);
            *(float2*)(C + (size_t)row * DD + col) =
                make_float2(c[mt][nt][0] + bb.x, c[mt][nt][1] + bb.y);
            *(float2*)(C + (size_t)(row + 8) * DD + col) =
                make_float2(c[mt][nt][2] + bb.x, c[mt][nt][3] + bb.y);
        }
    }
}

// ---------------------------------------------------------------------------
// tf32 MMA flash attention, fragment-layout smem. Br=128, Bc=64, DH=64.
// 256 threads = 8 warps; warp w owns query rows [16w, 16w+16).
// ---------------------------------------------------------------------------
#define QF_SZ (64 * ABLK)    // 8448 floats (8 warps x 8 ktiles)
#define KF_SZ (64 * BBLK)    // 4352 floats (8 ntiles x 8 ktiles)
#define VF_SZ (64 * BBLK)
#define PF_SZ (64 * ABLK)
#define FLASH_SMEM ((QF_SZ + KF_SZ + VF_SZ + PF_SZ) * 4)   // 102400 B

__global__ __launch_bounds__(256) void flash_frag(
    const float* __restrict__ Q, const float* __restrict__ K,
    const float* __restrict__ V, const float* __restrict__ lam,
    float* __restrict__ O)
{
    extern __shared__ float sm[];
    float* Qf = sm;
    float* Kf = sm + QF_SZ;
    float* Vf = Kf + KF_SZ;
    float* Pf = Vf + VF_SZ;

    const int tid  = threadIdx.x;
    const int warp = tid >> 5;
    const int lane = tid & 31;
    const int g    = lane >> 2;
    const int tig  = lane & 3;
    const int sl4  = swz(lane) * 4;
    const int sl2  = swz(lane) * 2;

    const int bh = blockIdx.y;
    const int b  = bh >> 4;
    const int h  = bh & 15;
    const int i0 = blockIdx.x << 7;       // 128 rows per block

    const float fac = 0.125f * lam[h];

    // ---- Q fill (once): 128x64, fragment layout, pre-scaled ----
    {
        const float* qp = Q + (size_t)(b * SS + i0) * DD + h * DHH;
        #pragma unroll
        for (int i = 0; i < 8; i++) {
            int idx = tid + i * 256;
            int r = idx >> 4, dg = (idx & 15) << 2;
            float4 v = *(const float4*)(qp + (size_t)r * DD + dg);
            int w = r >> 4, rr = r & 15;
            int gq = rr & 7, hi = rr >> 3;
            int kt = dg >> 3, half = (dg >> 2) & 1;
            float* blk = Qf + (w * 8 + kt) * ABLK;
            int reg = hi + 2 * half;
            float vv[4] = {v.x * fac, v.y * fac, v.z * fac, v.w * fac};
            #pragma unroll
            for (int j = 0; j < 4; j++)
                blk[swz(4 * gq + j) * 4 + reg] = to_tf32(vv[j]);
        }
    }

    float o[8][4];
    #pragma unroll
    for (int nt = 0; nt < 8; nt++)
        #pragma unroll
        for (int r = 0; r < 4; r++) o[nt][r] = 0.f;
    float m0 = -INFINITY, m1 = -INFINITY, l0 = 0.f, l1 = 0.f;

    const float* kp0 = K + (size_t)b * SS * DD + h * DHH;
    const float* vp0 = V + (size_t)b * SS * DD + h * DHH;

    for (int jt = 0; jt < SS / 64; jt++) {
        __syncthreads();
        const float* kp = kp0 + (size_t)jt * 64 * DD;
        const float* vp = vp0 + (size_t)jt * 64 * DD;
        // ---- K/V fill: 64x64 each ----
        #pragma unroll
        for (int i = 0; i < 4; i++) {
            int idx = tid + i * 256;
            int cc = idx >> 4, dg = (idx & 15) << 2;
            // K: b-frag indexed by (col cc, k-dim d)
            {
                float4 kv = *(const float4*)(kp + (size_t)cc * DD + dg);
                int nt = cc >> 3, gk = cc & 7;
                int kt = dg >> 3, half = (dg >> 2) & 1;
                float* blk = Kf + (nt * 8 + kt) * BBLK;
                float vv[4] = {kv.x, kv.y, kv.z, kv.w};
                #pragma unroll
                for (int j = 0; j < 4; j++)
                    blk[swz(4 * gk + j) * 2 + half] = to_tf32(vv[j]);
            }
            // V: b-frag indexed by (n=d, k=row cc)
            {
                float4 vv4 = *(const float4*)(vp + (size_t)cc * DD + dg);
                int ktv = cc >> 3, halfv = (cc >> 2) & 1, tv = cc & 3;
                float vv[4] = {vv4.x, vv4.y, vv4.z, vv4.w};
                #pragma unroll
                for (int j = 0; j < 4; j++) {
                    int d = dg + j;
                    float* blk = Vf + ((d >> 3) * 8 + ktv) * BBLK;
                    blk[swz(4 * (d & 7) + tv) * 2 + halfv] = to_tf32(vv[j]);
                }
            }
        }
        __syncthreads();

        // ---- S = Q K^T ----
        float s[8][4];
        #pragma unroll
        for (int nt = 0; nt < 8; nt++)
            #pragma unroll
            for (int r = 0; r < 4; r++) s[nt][r] = 0.f;

        #pragma unroll
        for (int kt = 0; kt < 8; kt++) {
            float a[4];
            *(float4*)a = *(const float4*)(Qf + (warp * 8 + kt) * ABLK + sl4);
            #pragma unroll
            for (int nt = 0; nt < 8; nt++) {
                float bb[2];
                *(float2*)bb = *(const float2*)(Kf + (nt * 8 + kt) * BBLK + sl2);
                mma_tf32(s[nt], a, bb);
            }
        }

        // ---- online softmax (rows g and g+8 of warp tile) ----
        float mx0 = -INFINITY, mx1 = -INFINITY;
        #pragma unroll
        for (int nt = 0; nt < 8; nt++) {
            mx0 = fmaxf(mx0, fmaxf(s[nt][0], s[nt][1]));
            mx1 = fmaxf(mx1, fmaxf(s[nt][2], s[nt][3]));
        }
        mx0 = fmaxf(mx0, __shfl_xor_sync(0xffffffffu, mx0, 1));
        mx0 = fmaxf(mx0, __shfl_xor_sync(0xffffffffu, mx0, 2));
        mx1 = fmaxf(mx1, __shfl_xor_sync(0xffffffffu, mx1, 1));
        mx1 = fmaxf(mx1, __shfl_xor_sync(0xffffffffu, mx1, 2));

        float mn0 = fmaxf(m0, mx0);
        float mn1 = fmaxf(m1, mx1);
        float al0 = __expf(m0 - mn0);
        float al1 = __expf(m1 - mn1);
        float lt0 = 0.f, lt1 = 0.f;
        #pragma unroll
        for (int nt = 0; nt < 8; nt++) {
            s[nt][0] = __expf(s[nt][0] - mn0); lt0 += s[nt][0];
            s[nt][1] = __expf(s[nt][1] - mn0); lt0 += s[nt][1];
            s[nt][2] = __expf(s[nt][2] - mn1); lt1 += s[nt][2];
            s[nt][3] = __expf(s[nt][3] - mn1); lt1 += s[nt][3];
        }
        lt0 += __shfl_xor_sync(0xffffffffu, lt0, 1);
        lt0 += __shfl_xor_sync(0xffffffffu, lt0, 2);
        lt1 += __shfl_xor_sync(0xffffffffu, lt1, 1);
        lt1 += __shfl_xor_sync(0xffffffffu, lt1, 2);
        l0 = l0 * al0 + lt0;
        l1 = l1 * al1 + lt1;
        m0 = mn0;
        m1 = mn1;
        #pragma unroll
        for (int nt = 0; nt < 8; nt++) {
            o[nt][0] *= al0; o[nt][1] *= al0;
            o[nt][2] *= al1; o[nt][3] *= al1;
        }

        // ---- P staging into A-frag layout (warp-private region) ----
        __syncwarp();
        {
            int halfP = tig >> 1;
            int t2 = (tig & 1) * 2;
            #pragma unroll
            for (int nt = 0; nt < 8; nt++) {
                float* blk = Pf + (warp * 8 + nt) * ABLK;
                int l0i = swz(4 * g + t2) * 4;
                int l1i = swz(4 * g + t2 + 1) * 4;
                blk[l0i + 2 * halfP]     = to_tf32(s[nt][0]);
                blk[l1i + 2 * halfP]     = to_tf32(s[nt][1]);
                blk[l0i + 1 + 2 * halfP] = to_tf32(s[nt][2]);
                blk[l1i + 1 + 2 * halfP] = to_tf32(s[nt][3]);
            }
        }
        __syncwarp();

        // ---- O += P @ V ----
        #pragma unroll
        for (int kt = 0; kt < 8; kt++) {
            float a[4];
            *(float4*)a = *(const float4*)(Pf + (warp * 8 + kt) * ABLK + sl4);
            #pragma unroll
            for (int nt = 0; nt < 8; nt++) {
                float bb[2];
                *(float2*)bb = *(const float2*)(Vf + (nt * 8 + kt) * BBLK + sl2);
                mma_tf32(o[nt], a, bb);
            }
        }
    }

    float inv0 = 1.f / l0;
    float inv1 = 1.f / l1;
    float* op0 = O + (size_t)(b * SS + i0 + warp * 16 + g) * DD + h * DHH;
    float* op1 = op0 + 8 * DD;
    #pragma unroll
    for (int nt = 0; nt < 8; nt++) {
        *(float2*)(op0 + nt * 8 + 2 * tig) =
            make_float2(o[nt][0] * inv0, o[nt][1] * inv0);
        *(float2*)(op1 + nt * 8 + 2 * tig) =
            make_float2(o[nt][2] * inv1, o[nt][3] * inv1);
    }
}

// ---------------------------------------------------------------------------
// GroupNorm stats: per (b,h), mean/var over (S, DH)
// ---------------------------------------------------------------------------
__global__ __launch_bounds__(256) void gn_stats(const float* __restrict__ O,
                                                float* __restrict__ mean,
                                                float* __restrict__ rstd)
{
    const int bh = blockIdx.x;
    const int b = bh >> 4;
    const int h = bh & 15;
    const float* base = O + ((size_t)b * SS * HH + h) * DHH;

    double sum = 0.0, sumsq = 0.0;
    for (int idx = threadIdx.x; idx < SS * DHH / 4; idx += 256) {
        int s_ = idx >> 4;
        int dg = (idx & 15) << 2;
        float4 v = *(const float4*)(base + (size_t)s_ * DD + dg);
        sum   += (double)v.x + (double)v.y + (double)v.z + (double)v.w;
        sumsq += (double)v.x * v.x + (double)v.y * v.y + (double)v.z * v.z + (double)v.w * v.w;
    }
    const int lane = threadIdx.x & 31;
    const int warp = threadIdx.x >> 5;
    #pragma unroll
    for (int off = 16; off > 0; off >>= 1) {
        sum   += __shfl_xor_sync(0xffffffffu, sum, off);
        sumsq += __shfl_xor_sync(0xffffffffu, sumsq, off);
    }
    __shared__ double ws[8], wq[8];
    if (lane == 0) { ws[warp] = sum; wq[warp] = sumsq; }
    __syncthreads();
    if (threadIdx.x == 0) {
        double ts = 0.0, tq = 0.0;
        #pragma unroll
        for (int i = 0; i < 8; i++) { ts += ws[i]; tq += wq[i]; }
        double n = (double)SS * DHH;
        double mu = ts / n;
        double var = tq / n - mu * mu;
        mean[bh] = (float)mu;
        rstd[bh] = (float)(1.0 / sqrt(var + (double)GN_EPS));
    }
}

// ---------------------------------------------------------------------------
extern "C" void kernel_launch(void* const* d_in, const int* in_sizes, int n_in,
                              void* d_out, int out_size) {
    const float* x   = (const float*)d_in[0];
    const float* Wq  = (const float*)d_in[1];
    const float* bq  = (const float*)d_in[2];
    const float* Wk  = (const float*)d_in[3];
    const float* bk  = (const float*)d_in[4];
    const float* Wv  = (const float*)d_in[5];
    const float* bv  = (const float*)d_in[6];
    const float* Wo  = (const float*)d_in[7];
    const float* bo  = (const float*)d_in[8];
    const float* lq1 = (const float*)d_in[9];
    const float* lk1 = (const float*)d_in[10];
    const float* lq2 = (const float*)d_in[11];
    const float* lk2 = (const float*)d_in[12];
    const float* gnw = (const float*)d_in[13];
    const float* gnb = (const float*)d_in[14];
    float* y = (float*)d_out;

    float *Qp, *Kp, *Vp, *AOp, *lamp, *meanp, *rstdp;
    cudaGetSymbolAddress((void**)&Qp,    g_Q);
    cudaGetSymbolAddress((void**)&Kp,    g_K);
    cudaGetSymbolAddress((void**)&Vp,    g_V);
    cudaGetSymbolAddress((void**)&AOp,   g_AO);
    cudaGetSymbolAddress((void**)&lamp,  g_lam);
    cudaGetSymbolAddress((void**)&meanp, g_mean);
    cudaGetSymbolAddress((void**)&rstdp, g_rstd);

    static int attr_set = 0;
    if (!attr_set) {
        cudaFuncSetAttribute(flash_frag, cudaFuncAttributeMaxDynamicSharedMemorySize,
                             FLASH_SMEM);
        attr_set = 1;
    }

    lambda_kernel<<<1, HH * 32>>>(lq1, lk1, lq2, lk2, lamp);

    dim3 ggrid(DD / 128, MM / 128);   // (8, 32)
    gemm_frag<0><<<ggrid, 256>>>(x, Wq, bq, Qp, nullptr, nullptr, nullptr, nullptr);
    gemm_frag<0><<<ggrid, 256>>>(x, Wk, bk, Kp, nullptr, nullptr, nullptr, nullptr);
    gemm_frag<0><<<ggrid, 256>>>(x, Wv, bv, Vp, nullptr, nullptr, nullptr, nullptr);

    flash_frag<<<dim3(SS / 128, BB * HH), 256, FLASH_SMEM>>>(Qp, Kp, Vp, lamp, AOp);

    gn_stats<<<BB * HH, 256>>>(AOp, meanp, rstdp);

    gemm_frag<1><<<ggrid, 256>>>(AOp, Wo, bo, y, meanp, rstdp, gnw, gnb);
}

// round 5
// speedup vs baseline: 1.1107x; 1.1107x over previous
#include <cuda_runtime.h>
#include <math.h>
#include <stdint.h>

// Problem constants
#define BB 2
#define SS 2048
#define DD 1024
#define HH 16
#define DHH 64
#define MM (BB*SS)          // 4096 rows
#define LAMBDA_INIT 0.8f
#define GN_EPS 1e-5f

// Scratch (device globals; no allocation allowed)
__device__ float g_Q[MM*DD];
__device__ float g_K[MM*DD];
__device__ float g_V[MM*DD];
__device__ float g_AO[MM*DD];   // attention output [B,S,H,DH]
__device__ float g_lam[HH];
__device__ float g_mean[BB*HH];
__device__ float g_rstd[BB*HH];

// ---------------------------------------------------------------------------
// helpers: tf32 convert + m16n8k8 tf32 mma
// ---------------------------------------------------------------------------
__device__ __forceinline__ float to_tf32(float x) {
    unsigned u;
    asm("cvt.rna.tf32.f32 %0, %1;" : "=r"(u) : "f"(x));
    return __uint_as_float(u);
}

__device__ __forceinline__ void mma_tf32(float* c, const float* a, const float* b) {
    const unsigned* A = reinterpret_cast<const unsigned*>(a);
    const unsigned* B = reinterpret_cast<const unsigned*>(b);
    asm volatile(
        "mma.sync.aligned.m16n8k8.row.col.f32.tf32.tf32.f32 "
        "{%0,%1,%2,%3}, {%4,%5,%6,%7}, {%8,%9}, {%0,%1,%2,%3};\n"
        : "+f"(c[0]), "+f"(c[1]), "+f"(c[2]), "+f"(c[3])
        : "r"(A[0]), "r"(A[1]), "r"(A[2]), "r"(A[3]),
          "r"(B[0]), "r"(B[1]));
}

// ---------------------------------------------------------------------------
// lambda[h] = exp(<lq1,lk1>) - exp(<lq2,lk2>) + 0.8  (one warp/head)
// ---------------------------------------------------------------------------
__global__ void lambda_kernel(const float* __restrict__ lq1, const float* __restrict__ lk1,
                              const float* __restrict__ lq2, const float* __restrict__ lk2,
                              float* __restrict__ lam) {
    int h = threadIdx.x >> 5;
    int lane = threadIdx.x & 31;
    const float* a1 = lq1 + h * DHH;
    const float* b1 = lk1 + h * DHH;
    const float* a2 = lq2 + h * DHH;
    const float* b2 = lk2 + h * DHH;
    float s1 = a1[lane] * b1[lane] + a1[lane + 32] * b1[lane + 32];
    float s2 = a2[lane] * b2[lane] + a2[lane + 32] * b2[lane + 32];
    #pragma unroll
    for (int off = 16; off > 0; off >>= 1) {
        s1 += __shfl_xor_sync(0xffffffffu, s1, off);
        s2 += __shfl_xor_sync(0xffffffffu, s2, off);
    }
    if (lane == 0) lam[h] = expf(s1) - expf(s2) + LAMBDA_INIT;
}

// ---------------------------------------------------------------------------
// tf32 tensor-core GEMM core (round-2 proven inner loop).
// C[4096,1024] tile at (bm, bn) = A[4096,1024] @ B[1024,1024] + bias.
// BM=128 BN=128 BK=16, 256 threads = 8 warps (2x4), warp tile 64x32,
// double-buffered smem.
// FUSE=1: A element -> ((A - mean[b,h]) * rstd[b,h]) * gnw[k] + gnb[k]
// ---------------------------------------------------------------------------
template<int FUSE>
__device__ __forceinline__ void gemm_core(
    float (*As)[128][20], float (*Bs)[16][136],
    const float* __restrict__ A, const float* __restrict__ B,
    const float* __restrict__ bias, float* __restrict__ C,
    int bm, int bn,
    const float* __restrict__ mean, const float* __restrict__ rstd,
    const float* __restrict__ gnw, const float* __restrict__ gnb)
{
    const int tid  = threadIdx.x;
    const int warp = tid >> 5;
    const int lane = tid & 31;
    const int g    = lane >> 2;
    const int tig  = lane & 3;
    const int wm   = warp >> 2;    // 0..1
    const int wn   = warp & 3;     // 0..3

    int arow[2], akc[2], bkr[2], bnc[2];
    #pragma unroll
    for (int i = 0; i < 2; i++) {
        int idx = tid + i * 256;
        arow[i] = idx >> 2;          // 0..127
        akc[i]  = (idx & 3) << 2;    // 0,4,8,12
        bkr[i]  = idx >> 5;          // 0..15
        bnc[i]  = (idx & 31) << 2;   // 0..124
    }

    float c[4][4][4];
    #pragma unroll
    for (int mt = 0; mt < 4; mt++)
        #pragma unroll
        for (int nt = 0; nt < 4; nt++)
            #pragma unroll
            for (int r = 0; r < 4; r++) c[mt][nt][r] = 0.f;

    float4 fa[2], fb[2];
    const int NT = DD / 16;

    auto do_fetch = [&](int kt) {
        #pragma unroll
        for (int i = 0; i < 2; i++) {
            fa[i] = *(const float4*)(A + (size_t)(bm + arow[i]) * DD + kt + akc[i]);
            if (FUSE) {
                int rowg = bm + arow[i];
                int bi   = rowg >> 11;          // row / 2048
                int k    = kt + akc[i];
                int hh   = k >> 6;
                float mu = mean[bi * HH + hh];
                float rs = rstd[bi * HH + hh];
                float4 w  = *(const float4*)(gnw + k);
                float4 gb = *(const float4*)(gnb + k);
                fa[i].x = (fa[i].x - mu) * rs * w.x + gb.x;
                fa[i].y = (fa[i].y - mu) * rs * w.y + gb.y;
                fa[i].z = (fa[i].z - mu) * rs * w.z + gb.z;
                fa[i].w = (fa[i].w - mu) * rs * w.w + gb.w;
            }
            fb[i] = *(const float4*)(B + (size_t)(kt + bkr[i]) * DD + bn + bnc[i]);
        }
    };
    auto do_store = [&](int buf) {
        #pragma unroll
        for (int i = 0; i < 2; i++) {
            As[buf][arow[i]][akc[i] + 0] = to_tf32(fa[i].x);
            As[buf][arow[i]][akc[i] + 1] = to_tf32(fa[i].y);
            As[buf][arow[i]][akc[i] + 2] = to_tf32(fa[i].z);
            As[buf][arow[i]][akc[i] + 3] = to_tf32(fa[i].w);
            Bs[buf][bkr[i]][bnc[i] + 0] = to_tf32(fb[i].x);
            Bs[buf][bkr[i]][bnc[i] + 1] = to_tf32(fb[i].y);
            Bs[buf][bkr[i]][bnc[i] + 2] = to_tf32(fb[i].z);
            Bs[buf][bkr[i]][bnc[i] + 3] = to_tf32(fb[i].w);
        }
    };

    do_fetch(0);
    do_store(0);
    __syncthreads();

    for (int t = 0; t < NT; t++) {
        int buf = t & 1;
        if (t + 1 < NT) do_fetch((t + 1) * 16);

        #pragma unroll
        for (int kk = 0; kk < 16; kk += 8) {
            float a[4][4], b[4][2];
            #pragma unroll
            for (int mt = 0; mt < 4; mt++) {
                int r0 = wm * 64 + mt * 16 + g;
                a[mt][0] = As[buf][r0][kk + tig];
                a[mt][1] = As[buf][r0 + 8][kk + tig];
                a[mt][2] = As[buf][r0][kk + tig + 4];
                a[mt][3] = As[buf][r0 + 8][kk + tig + 4];
            }
            #pragma unroll
            for (int nt = 0; nt < 4; nt++) {
                int cn = wn * 32 + nt * 8 + g;
                b[nt][0] = Bs[buf][kk + tig][cn];
                b[nt][1] = Bs[buf][kk + tig + 4][cn];
            }
            #pragma unroll
            for (int mt = 0; mt < 4; mt++)
                #pragma unroll
                for (int nt = 0; nt < 4; nt++)
                    mma_tf32(c[mt][nt], a[mt], b[nt]);
        }

        if (t + 1 < NT) do_store(buf ^ 1);
        __syncthreads();
    }

    // epilogue + bias
    #pragma unroll
    for (int mt = 0; mt < 4; mt++) {
        int row = bm + wm * 64 + mt * 16 + g;
        #pragma unroll
        for (int nt = 0; nt < 4; nt++) {
            int col = bn + wn * 32 + nt * 8 + 2 * tig;
            float2 bb = *(const float2*)(bias + col);
            *(float2*)(C + (size_t)row * DD + col) =
                make_float2(c[mt][nt][0] + bb.x, c[mt][nt][1] + bb.y);
            *(float2*)(C + (size_t)(row + 8) * DD + col) =
                make_float2(c[mt][nt][2] + bb.x, c[mt][nt][3] + bb.y);
        }
    }
}

// Fused Q/K/V projection: grid (24, 32); x-blocks 0-7 -> Q, 8-15 -> K, 16-23 -> V
__global__ __launch_bounds__(256, 2) void gemm_qkv(
    const float* __restrict__ x,
    const float* __restrict__ Wq, const float* __restrict__ Wk, const float* __restrict__ Wv,
    const float* __restrict__ bq, const float* __restrict__ bk, const float* __restrict__ bv,
    float* __restrict__ Q, float* __restrict__ K, float* __restrict__ V)
{
    __shared__ float As[2][128][20];
    __shared__ float Bs[2][16][136];

    int sel = blockIdx.x >> 3;
    const float* B    = (sel == 0) ? Wq : (sel == 1) ? Wk : Wv;
    const float* bias = (sel == 0) ? bq : (sel == 1) ? bk : bv;
    float*       C    = (sel == 0) ? Q  : (sel == 1) ? K  : V;
    int bn = (blockIdx.x & 7) * 128;
    int bm = blockIdx.y * 128;

    gemm_core<0>(As, Bs, x, B, bias, C, bm, bn, nullptr, nullptr, nullptr, nullptr);
}

// O projection with fused GroupNorm on the A operand
__global__ __launch_bounds__(256, 2) void gemm_o(
    const float* __restrict__ AO, const float* __restrict__ Wo,
    const float* __restrict__ bo, float* __restrict__ y,
    const float* __restrict__ mean, const float* __restrict__ rstd,
    const float* __restrict__ gnw, const float* __restrict__ gnb)
{
    __shared__ float As[2][128][20];
    __shared__ float Bs[2][16][136];
    gemm_core<1>(As, Bs, AO, Wo, bo, y,
                 blockIdx.y * 128, blockIdx.x * 128, mean, rstd, gnw, gnb);
}

// ---------------------------------------------------------------------------
// tf32 tensor-core flash attention (round-2 proven version, unchanged).
// Br=Bc=64, DH=64. 128 threads = 4 warps; warp w owns rows [16w,16w+16).
// ---------------------------------------------------------------------------
__global__ __launch_bounds__(128) void flash_tf32(
    const float* __restrict__ Q, const float* __restrict__ K,
    const float* __restrict__ V, const float* __restrict__ lam,
    float* __restrict__ O)
{
    extern __shared__ float smf[];
    float (*Qs)[68] = (float(*)[68])(smf);
    float (*Ks)[68] = (float(*)[68])(smf + 64 * 68);
    float (*Ps)[68] = (float(*)[68])(smf + 2 * 64 * 68);
    float (*Vs)[72] = (float(*)[72])(smf + 3 * 64 * 68);

    const int tid  = threadIdx.x;
    const int warp = tid >> 5;
    const int lane = tid & 31;
    const int g    = lane >> 2;
    const int tig  = lane & 3;
    const int r_q  = (warp << 4) + g;

    const int bh = blockIdx.y;
    const int b  = bh >> 4;
    const int h  = bh & 15;
    const int i0 = blockIdx.x << 6;

    const float fac = 0.125f * lam[h];

    {
        const float* qp = Q + (size_t)(b * SS + i0) * DD + h * DHH;
        #pragma unroll
        for (int i = 0; i < 8; i++) {
            int idx = tid + i * 128;
            int r = idx >> 4, dg = (idx & 15) << 2;
            float4 v = *(const float4*)(qp + (size_t)r * DD + dg);
            Qs[r][dg + 0] = to_tf32(v.x * fac);
            Qs[r][dg + 1] = to_tf32(v.y * fac);
            Qs[r][dg + 2] = to_tf32(v.z * fac);
            Qs[r][dg + 3] = to_tf32(v.w * fac);
        }
    }

    float o[8][4];
    #pragma unroll
    for (int nt = 0; nt < 8; nt++)
        #pragma unroll
        for (int r = 0; r < 4; r++) o[nt][r] = 0.f;
    float m0 = -INFINITY, m1 = -INFINITY, l0 = 0.f, l1 = 0.f;

    const float* kp0 = K + (size_t)b * SS * DD + h * DHH;
    const float* vp0 = V + (size_t)b * SS * DD + h * DHH;

    for (int jt = 0; jt < SS / 64; jt++) {
        __syncthreads();
        const float* kp = kp0 + (size_t)jt * 64 * DD;
        const float* vp = vp0 + (size_t)jt * 64 * DD;
        #pragma unroll
        for (int i = 0; i < 8; i++) {
            int idx = tid + i * 128;
            int r = idx >> 4, dg = (idx & 15) << 2;
            float4 kv = *(const float4*)(kp + (size_t)r * DD + dg);
            Ks[r][dg + 0] = to_tf32(kv.x);
            Ks[r][dg + 1] = to_tf32(kv.y);
            Ks[r][dg + 2] = to_tf32(kv.z);
            Ks[r][dg + 3] = to_tf32(kv.w);
            float4 vv = *(const float4*)(vp + (size_t)r * DD + dg);
            Vs[r][dg + 0] = to_tf32(vv.x);
            Vs[r][dg + 1] = to_tf32(vv.y);
            Vs[r][dg + 2] = to_tf32(vv.z);
            Vs[r][dg + 3] = to_tf32(vv.w);
        }
        __syncthreads();

        float s[8][4];
        #pragma unroll
        for (int nt = 0; nt < 8; nt++)
            #pragma unroll
            for (int r = 0; r < 4; r++) s[nt][r] = 0.f;

        #pragma unroll
        for (int kk = 0; kk < 64; kk += 8) {
            float a[4];
            a[0] = Qs[r_q][kk + tig];
            a[1] = Qs[r_q + 8][kk + tig];
            a[2] = Qs[r_q][kk + tig + 4];
            a[3] = Qs[r_q + 8][kk + tig + 4];
            #pragma unroll
            for (int nt = 0; nt < 8; nt++) {
                float bfr[2];
                bfr[0] = Ks[nt * 8 + g][kk + tig];
                bfr[1] = Ks[nt * 8 + g][kk + tig + 4];
                mma_tf32(s[nt], a, bfr);
            }
        }

        float mx0 = -INFINITY, mx1 = -INFINITY;
        #pragma unroll
        for (int nt = 0; nt < 8; nt++) {
            mx0 = fmaxf(mx0, fmaxf(s[nt][0], s[nt][1]));
            mx1 = fmaxf(mx1, fmaxf(s[nt][2], s[nt][3]));
        }
        mx0 = fmaxf(mx0, __shfl_xor_sync(0xffffffffu, mx0, 1));
        mx0 = fmaxf(mx0, __shfl_xor_sync(0xffffffffu, mx0, 2));
        mx1 = fmaxf(mx1, __shfl_xor_sync(0xffffffffu, mx1, 1));
        mx1 = fmaxf(mx1, __shfl_xor_sync(0xffffffffu, mx1, 2));

        float mn0 = fmaxf(m0, mx0);
        float mn1 = fmaxf(m1, mx1);
        float al0 = __expf(m0 - mn0);
        float al1 = __expf(m1 - mn1);
        float lt0 = 0.f, lt1 = 0.f;
        #pragma unroll
        for (int nt = 0; nt < 8; nt++) {
            s[nt][0] = __expf(s[nt][0] - mn0); lt0 += s[nt][0];
            s[nt][1] = __expf(s[nt][1] - mn0); lt0 += s[nt][1];
            s[nt][2] = __expf(s[nt][2] - mn1); lt1 += s[nt][2];
            s[nt][3] = __expf(s[nt][3] - mn1); lt1 += s[nt][3];
        }
        lt0 += __shfl_xor_sync(0xffffffffu, lt0, 1);
        lt0 += __shfl_xor_sync(0xffffffffu, lt0, 2);
        lt1 += __shfl_xor_sync(0xffffffffu, lt1, 1);
        lt1 += __shfl_xor_sync(0xffffffffu, lt1, 2);
        l0 = l0 * al0 + lt0;
        l1 = l1 * al1 + lt1;
        m0 = mn0;
        m1 = mn1;
        #pragma unroll
        for (int nt = 0; nt < 8; nt++) {
            o[nt][0] *= al0; o[nt][1] *= al0;
            o[nt][2] *= al1; o[nt][3] *= al1;
        }

        #pragma unroll
        for (int nt = 0; nt < 8; nt++) {
            Ps[r_q][nt * 8 + 2 * tig]         = to_tf32(s[nt][0]);
            Ps[r_q][nt * 8 + 2 * tig + 1]     = to_tf32(s[nt][1]);
            Ps[r_q + 8][nt * 8 + 2 * tig]     = to_tf32(s[nt][2]);
            Ps[r_q + 8][nt * 8 + 2 * tig + 1] = to_tf32(s[nt][3]);
        }
        __syncwarp();

        #pragma unroll
        for (int kk = 0; kk < 64; kk += 8) {
            float a[4];
            a[0] = Ps[r_q][kk + tig];
            a[1] = Ps[r_q + 8][kk + tig];
            a[2] = Ps[r_q][kk + tig + 4];
            a[3] = Ps[r_q + 8][kk + tig + 4];
            #pragma unroll
            for (int nt = 0; nt < 8; nt++) {
                float bfr[2];
                bfr[0] = Vs[kk + tig][nt * 8 + g];
                bfr[1] = Vs[kk + tig + 4][nt * 8 + g];
                mma_tf32(o[nt], a, bfr);
            }
        }
    }

    float inv0 = 1.f / l0;
    float inv1 = 1.f / l1;
    float* op0 = O + (size_t)(b * SS + i0 + r_q) * DD + h * DHH;
    float* op1 = op0 + 8 * DD;
    #pragma unroll
    for (int nt = 0; nt < 8; nt++) {
        *(float2*)(op0 + nt * 8 + 2 * tig) =
            make_float2(o[nt][0] * inv0, o[nt][1] * inv0);
        *(float2*)(op1 + nt * 8 + 2 * tig) =
            make_float2(o[nt][2] * inv1, o[nt][3] * inv1);
    }
}

// ---------------------------------------------------------------------------
// GroupNorm stats: per (b,h), mean/var over (S, DH)
// ---------------------------------------------------------------------------
__global__ __launch_bounds__(256) void gn_stats(const float* __restrict__ O,
                                                float* __restrict__ mean,
                                                float* __restrict__ rstd)
{
    const int bh = blockIdx.x;
    const int b = bh >> 4;
    const int h = bh & 15;
    const float* base = O + ((size_t)b * SS * HH + h) * DHH;

    double sum = 0.0, sumsq = 0.0;
    for (int idx = threadIdx.x; idx < SS * DHH / 4; idx += 256) {
        int s_ = idx >> 4;
        int dg = (idx & 15) << 2;
        float4 v = *(const float4*)(base + (size_t)s_ * DD + dg);
        sum   += (double)v.x + (double)v.y + (double)v.z + (double)v.w;
        sumsq += (double)v.x * v.x + (double)v.y * v.y + (double)v.z * v.z + (double)v.w * v.w;
    }
    const int lane = threadIdx.x & 31;
    const int warp = threadIdx.x >> 5;
    #pragma unroll
    for (int off = 16; off > 0; off >>= 1) {
        sum   += __shfl_xor_sync(0xffffffffu, sum, off);
        sumsq += __shfl_xor_sync(0xffffffffu, sumsq, off);
    }
    __shared__ double ws[8], wq[8];
    if (lane == 0) { ws[warp] = sum; wq[warp] = sumsq; }
    __syncthreads();
    if (threadIdx.x == 0) {
        double ts = 0.0, tq = 0.0;
        #pragma unroll
        for (int i = 0; i < 8; i++) { ts += ws[i]; tq += wq[i]; }
        double n = (double)SS * DHH;
        double mu = ts / n;
        double var = tq / n - mu * mu;
        mean[bh] = (float)mu;
        rstd[bh] = (float)(1.0 / sqrt(var + (double)GN_EPS));
    }
}

// ---------------------------------------------------------------------------
extern "C" void kernel_launch(void* const* d_in, const int* in_sizes, int n_in,
                              void* d_out, int out_size) {
    const float* x   = (const float*)d_in[0];
    const float* Wq  = (const float*)d_in[1];
    const float* bq  = (const float*)d_in[2];
    const float* Wk  = (const float*)d_in[3];
    const float* bk  = (const float*)d_in[4];
    const float* Wv  = (const float*)d_in[5];
    const float* bv  = (const float*)d_in[6];
    const float* Wo  = (const float*)d_in[7];
    const float* bo  = (const float*)d_in[8];
    const float* lq1 = (const float*)d_in[9];
    const float* lk1 = (const float*)d_in[10];
    const float* lq2 = (const float*)d_in[11];
    const float* lk2 = (const float*)d_in[12];
    const float* gnw = (const float*)d_in[13];
    const float* gnb = (const float*)d_in[14];
    float* y = (float*)d_out;

    float *Qp, *Kp, *Vp, *AOp, *lamp, *meanp, *rstdp;
    cudaGetSymbolAddress((void**)&Qp,    g_Q);
    cudaGetSymbolAddress((void**)&Kp,    g_K);
    cudaGetSymbolAddress((void**)&Vp,    g_V);
    cudaGetSymbolAddress((void**)&AOp,   g_AO);
    cudaGetSymbolAddress((void**)&lamp,  g_lam);
    cudaGetSymbolAddress((void**)&meanp, g_mean);
    cudaGetSymbolAddress((void**)&rstdp, g_rstd);

    static int attr_set = 0;
    if (!attr_set) {
        cudaFuncSetAttribute(flash_tf32, cudaFuncAttributeMaxDynamicSharedMemorySize,
                             (3 * 64 * 68 + 64 * 72) * 4);
        attr_set = 1;
    }

    lambda_kernel<<<1, HH * 32>>>(lq1, lk1, lq2, lk2, lamp);

    gemm_qkv<<<dim3(24, 32), 256>>>(x, Wq, Wk, Wv, bq, bk, bv, Qp, Kp, Vp);

    flash_tf32<<<dim3(SS / 64, BB * HH), 128, (3 * 64 * 68 + 64 * 72) * 4>>>(Qp, Kp, Vp, lamp, AOp);

    gn_stats<<<BB * HH, 256>>>(AOp, meanp, rstdp);

    gemm_o<<<dim3(8, 32), 256>>>(AOp, Wo, bo, y, meanp, rstdp, gnw, gnb);
}

// round 6
// speedup vs baseline: 1.2480x; 1.1236x over previous
#include <cuda_runtime.h>
#include <math.h>
#include <stdint.h>

// Problem constants
#define BB 2
#define SS 2048
#define DD 1024
#define HH 16
#define DHH 64
#define MM (BB*SS)          // 4096 rows
#define LAMBDA_INIT 0.8f
#define GN_EPS 1e-5f

// Scratch (device globals; no allocation allowed)
__device__ float g_Q[MM*DD];
__device__ float g_K[MM*DD];
__device__ float g_V[MM*DD];
__device__ float g_AO[MM*DD];   // attention output [B,S,H,DH]
__device__ float g_lam[HH];
__device__ float g_mean[BB*HH];
__device__ float g_rstd[BB*HH];
__device__ double g_part[BB*HH*8*2];   // [bh][part][{sum,sumsq}]

// ---------------------------------------------------------------------------
// helpers: tf32 convert + m16n8k8 tf32 mma
// ---------------------------------------------------------------------------
__device__ __forceinline__ float to_tf32(float x) {
    unsigned u;
    asm("cvt.rna.tf32.f32 %0, %1;" : "=r"(u) : "f"(x));
    return __uint_as_float(u);
}

__device__ __forceinline__ void mma_tf32(float* c, const float* a, const float* b) {
    const unsigned* A = reinterpret_cast<const unsigned*>(a);
    const unsigned* B = reinterpret_cast<const unsigned*>(b);
    asm volatile(
        "mma.sync.aligned.m16n8k8.row.col.f32.tf32.tf32.f32 "
        "{%0,%1,%2,%3}, {%4,%5,%6,%7}, {%8,%9}, {%0,%1,%2,%3};\n"
        : "+f"(c[0]), "+f"(c[1]), "+f"(c[2]), "+f"(c[3])
        : "r"(A[0]), "r"(A[1]), "r"(A[2]), "r"(A[3]),
          "r"(B[0]), "r"(B[1]));
}

// ---------------------------------------------------------------------------
// lambda[h] = exp(<lq1,lk1>) - exp(<lq2,lk2>) + 0.8  (one warp/head)
// ---------------------------------------------------------------------------
__global__ void lambda_kernel(const float* __restrict__ lq1, const float* __restrict__ lk1,
                              const float* __restrict__ lq2, const float* __restrict__ lk2,
                              float* __restrict__ lam) {
    int h = threadIdx.x >> 5;
    int lane = threadIdx.x & 31;
    const float* a1 = lq1 + h * DHH;
    const float* b1 = lk1 + h * DHH;
    const float* a2 = lq2 + h * DHH;
    const float* b2 = lk2 + h * DHH;
    float s1 = a1[lane] * b1[lane] + a1[lane + 32] * b1[lane + 32];
    float s2 = a2[lane] * b2[lane] + a2[lane + 32] * b2[lane + 32];
    #pragma unroll
    for (int off = 16; off > 0; off >>= 1) {
        s1 += __shfl_xor_sync(0xffffffffu, s1, off);
        s2 += __shfl_xor_sync(0xffffffffu, s2, off);
    }
    if (lane == 0) lam[h] = expf(s1) - expf(s2) + LAMBDA_INIT;
}

// ---------------------------------------------------------------------------
// tf32 tensor-core GEMM core (round-2 proven inner loop).
// BM=128 BN=128 BK=16, 256 threads = 8 warps (2x4), warp tile 64x32,
// double-buffered smem.
// FUSE=1: A element -> ((A - mean[b,h]) * rstd[b,h]) * gnw[k] + gnb[k]
// ---------------------------------------------------------------------------
template<int FUSE>
__device__ __forceinline__ void gemm_core(
    float (*As)[128][20], float (*Bs)[16][136],
    const float* __restrict__ A, const float* __restrict__ B,
    const float* __restrict__ bias, float* __restrict__ C,
    int bm, int bn,
    const float* __restrict__ mean, const float* __restrict__ rstd,
    const float* __restrict__ gnw, const float* __restrict__ gnb)
{
    const int tid  = threadIdx.x;
    const int warp = tid >> 5;
    const int lane = tid & 31;
    const int g    = lane >> 2;
    const int tig  = lane & 3;
    const int wm   = warp >> 2;    // 0..1
    const int wn   = warp & 3;     // 0..3

    int arow[2], akc[2], bkr[2], bnc[2];
    #pragma unroll
    for (int i = 0; i < 2; i++) {
        int idx = tid + i * 256;
        arow[i] = idx >> 2;          // 0..127
        akc[i]  = (idx & 3) << 2;    // 0,4,8,12
        bkr[i]  = idx >> 5;          // 0..15
        bnc[i]  = (idx & 31) << 2;   // 0..124
    }

    float c[4][4][4];
    #pragma unroll
    for (int mt = 0; mt < 4; mt++)
        #pragma unroll
        for (int nt = 0; nt < 4; nt++)
            #pragma unroll
            for (int r = 0; r < 4; r++) c[mt][nt][r] = 0.f;

    float4 fa[2], fb[2];
    const int NT = DD / 16;

    auto do_fetch = [&](int kt) {
        #pragma unroll
        for (int i = 0; i < 2; i++) {
            fa[i] = *(const float4*)(A + (size_t)(bm + arow[i]) * DD + kt + akc[i]);
            if (FUSE) {
                int rowg = bm + arow[i];
                int bi   = rowg >> 11;          // row / 2048
                int k    = kt + akc[i];
                int hh   = k >> 6;
                float mu = mean[bi * HH + hh];
                float rs = rstd[bi * HH + hh];
                float4 w  = *(const float4*)(gnw + k);
                float4 gb = *(const float4*)(gnb + k);
                fa[i].x = (fa[i].x - mu) * rs * w.x + gb.x;
                fa[i].y = (fa[i].y - mu) * rs * w.y + gb.y;
                fa[i].z = (fa[i].z - mu) * rs * w.z + gb.z;
                fa[i].w = (fa[i].w - mu) * rs * w.w + gb.w;
            }
            fb[i] = *(const float4*)(B + (size_t)(kt + bkr[i]) * DD + bn + bnc[i]);
        }
    };
    auto do_store = [&](int buf) {
        #pragma unroll
        for (int i = 0; i < 2; i++) {
            As[buf][arow[i]][akc[i] + 0] = to_tf32(fa[i].x);
            As[buf][arow[i]][akc[i] + 1] = to_tf32(fa[i].y);
            As[buf][arow[i]][akc[i] + 2] = to_tf32(fa[i].z);
            As[buf][arow[i]][akc[i] + 3] = to_tf32(fa[i].w);
            Bs[buf][bkr[i]][bnc[i] + 0] = to_tf32(fb[i].x);
            Bs[buf][bkr[i]][bnc[i] + 1] = to_tf32(fb[i].y);
            Bs[buf][bkr[i]][bnc[i] + 2] = to_tf32(fb[i].z);
            Bs[buf][bkr[i]][bnc[i] + 3] = to_tf32(fb[i].w);
        }
    };

    do_fetch(0);
    do_store(0);
    __syncthreads();

    for (int t = 0; t < NT; t++) {
        int buf = t & 1;
        if (t + 1 < NT) do_fetch((t + 1) * 16);

        #pragma unroll
        for (int kk = 0; kk < 16; kk += 8) {
            float a[4][4], b[4][2];
            #pragma unroll
            for (int mt = 0; mt < 4; mt++) {
                int r0 = wm * 64 + mt * 16 + g;
                a[mt][0] = As[buf][r0][kk + tig];
                a[mt][1] = As[buf][r0 + 8][kk + tig];
                a[mt][2] = As[buf][r0][kk + tig + 4];
                a[mt][3] = As[buf][r0 + 8][kk + tig + 4];
            }
            #pragma unroll
            for (int nt = 0; nt < 4; nt++) {
                int cn = wn * 32 + nt * 8 + g;
                b[nt][0] = Bs[buf][kk + tig][cn];
                b[nt][1] = Bs[buf][kk + tig + 4][cn];
            }
            #pragma unroll
            for (int mt = 0; mt < 4; mt++)
                #pragma unroll
                for (int nt = 0; nt < 4; nt++)
                    mma_tf32(c[mt][nt], a[mt], b[nt]);
        }

        if (t + 1 < NT) do_store(buf ^ 1);
        __syncthreads();
    }

    // epilogue + bias
    #pragma unroll
    for (int mt = 0; mt < 4; mt++) {
        int row = bm + wm * 64 + mt * 16 + g;
        #pragma unroll
        for (int nt = 0; nt < 4; nt++) {
            int col = bn + wn * 32 + nt * 8 + 2 * tig;
            float2 bb = *(const float2*)(bias + col);
            *(float2*)(C + (size_t)row * DD + col) =
                make_float2(c[mt][nt][0] + bb.x, c[mt][nt][1] + bb.y);
            *(float2*)(C + (size_t)(row + 8) * DD + col) =
                make_float2(c[mt][nt][2] + bb.x, c[mt][nt][3] + bb.y);
        }
    }
}

// Fused Q/K/V projection: grid (24, 32); x-blocks 0-7 -> Q, 8-15 -> K, 16-23 -> V
__global__ __launch_bounds__(256, 2) void gemm_qkv(
    const float* __restrict__ x,
    const float* __restrict__ Wq, const float* __restrict__ Wk, const float* __restrict__ Wv,
    const float* __restrict__ bq, const float* __restrict__ bk, const float* __restrict__ bv,
    float* __restrict__ Q, float* __restrict__ K, float* __restrict__ V)
{
    __shared__ float As[2][128][20];
    __shared__ float Bs[2][16][136];

    int sel = blockIdx.x >> 3;
    const float* B    = (sel == 0) ? Wq : (sel == 1) ? Wk : Wv;
    const float* bias = (sel == 0) ? bq : (sel == 1) ? bk : bv;
    float*       C    = (sel == 0) ? Q  : (sel == 1) ? K  : V;
    int bn = (blockIdx.x & 7) * 128;
    int bm = blockIdx.y * 128;

    gemm_core<0>(As, Bs, x, B, bias, C, bm, bn, nullptr, nullptr, nullptr, nullptr);
}

// O projection with fused GroupNorm on the A operand
__global__ __launch_bounds__(256, 2) void gemm_o(
    const float* __restrict__ AO, const float* __restrict__ Wo,
    const float* __restrict__ bo, float* __restrict__ y,
    const float* __restrict__ mean, const float* __restrict__ rstd,
    const float* __restrict__ gnw, const float* __restrict__ gnb)
{
    __shared__ float As[2][128][20];
    __shared__ float Bs[2][16][136];
    gemm_core<1>(As, Bs, AO, Wo, bo, y,
                 blockIdx.y * 128, blockIdx.x * 128, mean, rstd, gnw, gnb);
}

// ---------------------------------------------------------------------------
// tf32 tensor-core flash attention — persistent grid over 1024 tiles.
// Br=Bc=64, DH=64. 128 threads = 4 warps; warp w owns rows [16w,16w+16).
// ---------------------------------------------------------------------------
#define FLASH_TILES (BB * HH * (SS / 64))   // 1024
#define FLASH_SMEM ((3 * 64 * 68 + 64 * 72) * 4)

__global__ __launch_bounds__(128) void flash_tf32(
    const float* __restrict__ Q, const float* __restrict__ K,
    const float* __restrict__ V, const float* __restrict__ lam,
    float* __restrict__ O)
{
    extern __shared__ float smf[];
    float (*Qs)[68] = (float(*)[68])(smf);
    float (*Ks)[68] = (float(*)[68])(smf + 64 * 68);
    float (*Ps)[68] = (float(*)[68])(smf + 2 * 64 * 68);
    float (*Vs)[72] = (float(*)[72])(smf + 3 * 64 * 68);

    const int tid  = threadIdx.x;
    const int warp = tid >> 5;
    const int lane = tid & 31;
    const int g    = lane >> 2;
    const int tig  = lane & 3;
    const int r_q  = (warp << 4) + g;

    for (int tile = blockIdx.x; tile < FLASH_TILES; tile += gridDim.x) {
        const int bh = tile >> 5;
        const int it = tile & 31;
        const int b  = bh >> 4;
        const int h  = bh & 15;
        const int i0 = it << 6;
        const float fac = 0.125f * lam[h];

        __syncthreads();   // protect Qs refill vs lagging QK^T reads of prev tile

        {
            const float* qp = Q + (size_t)(b * SS + i0) * DD + h * DHH;
            #pragma unroll
            for (int i = 0; i < 8; i++) {
                int idx = tid + i * 128;
                int r = idx >> 4, dg = (idx & 15) << 2;
                float4 v = *(const float4*)(qp + (size_t)r * DD + dg);
                Qs[r][dg + 0] = to_tf32(v.x * fac);
                Qs[r][dg + 1] = to_tf32(v.y * fac);
                Qs[r][dg + 2] = to_tf32(v.z * fac);
                Qs[r][dg + 3] = to_tf32(v.w * fac);
            }
        }

        float o[8][4];
        #pragma unroll
        for (int nt = 0; nt < 8; nt++)
            #pragma unroll
            for (int r = 0; r < 4; r++) o[nt][r] = 0.f;
        float m0 = -INFINITY, m1 = -INFINITY, l0 = 0.f, l1 = 0.f;

        const float* kp0 = K + (size_t)b * SS * DD + h * DHH;
        const float* vp0 = V + (size_t)b * SS * DD + h * DHH;

        for (int jt = 0; jt < SS / 64; jt++) {
            __syncthreads();
            const float* kp = kp0 + (size_t)jt * 64 * DD;
            const float* vp = vp0 + (size_t)jt * 64 * DD;
            #pragma unroll
            for (int i = 0; i < 8; i++) {
                int idx = tid + i * 128;
                int r = idx >> 4, dg = (idx & 15) << 2;
                float4 kv = *(const float4*)(kp + (size_t)r * DD + dg);
                Ks[r][dg + 0] = to_tf32(kv.x);
                Ks[r][dg + 1] = to_tf32(kv.y);
                Ks[r][dg + 2] = to_tf32(kv.z);
                Ks[r][dg + 3] = to_tf32(kv.w);
                float4 vv = *(const float4*)(vp + (size_t)r * DD + dg);
                Vs[r][dg + 0] = to_tf32(vv.x);
                Vs[r][dg + 1] = to_tf32(vv.y);
                Vs[r][dg + 2] = to_tf32(vv.z);
                Vs[r][dg + 3] = to_tf32(vv.w);
            }
            __syncthreads();

            float s[8][4];
            #pragma unroll
            for (int nt = 0; nt < 8; nt++)
                #pragma unroll
                for (int r = 0; r < 4; r++) s[nt][r] = 0.f;

            #pragma unroll
            for (int kk = 0; kk < 64; kk += 8) {
                float a[4];
                a[0] = Qs[r_q][kk + tig];
                a[1] = Qs[r_q + 8][kk + tig];
                a[2] = Qs[r_q][kk + tig + 4];
                a[3] = Qs[r_q + 8][kk + tig + 4];
                #pragma unroll
                for (int nt = 0; nt < 8; nt++) {
                    float bfr[2];
                    bfr[0] = Ks[nt * 8 + g][kk + tig];
                    bfr[1] = Ks[nt * 8 + g][kk + tig + 4];
                    mma_tf32(s[nt], a, bfr);
                }
            }

            float mx0 = -INFINITY, mx1 = -INFINITY;
            #pragma unroll
            for (int nt = 0; nt < 8; nt++) {
                mx0 = fmaxf(mx0, fmaxf(s[nt][0], s[nt][1]));
                mx1 = fmaxf(mx1, fmaxf(s[nt][2], s[nt][3]));
            }
            mx0 = fmaxf(mx0, __shfl_xor_sync(0xffffffffu, mx0, 1));
            mx0 = fmaxf(mx0, __shfl_xor_sync(0xffffffffu, mx0, 2));
            mx1 = fmaxf(mx1, __shfl_xor_sync(0xffffffffu, mx1, 1));
            mx1 = fmaxf(mx1, __shfl_xor_sync(0xffffffffu, mx1, 2));

            float mn0 = fmaxf(m0, mx0);
            float mn1 = fmaxf(m1, mx1);
            float al0 = __expf(m0 - mn0);
            float al1 = __expf(m1 - mn1);
            float lt0 = 0.f, lt1 = 0.f;
            #pragma unroll
            for (int nt = 0; nt < 8; nt++) {
                s[nt][0] = __expf(s[nt][0] - mn0); lt0 += s[nt][0];
                s[nt][1] = __expf(s[nt][1] - mn0); lt0 += s[nt][1];
                s[nt][2] = __expf(s[nt][2] - mn1); lt1 += s[nt][2];
                s[nt][3] = __expf(s[nt][3] - mn1); lt1 += s[nt][3];
            }
            lt0 += __shfl_xor_sync(0xffffffffu, lt0, 1);
            lt0 += __shfl_xor_sync(0xffffffffu, lt0, 2);
            lt1 += __shfl_xor_sync(0xffffffffu, lt1, 1);
            lt1 += __shfl_xor_sync(0xffffffffu, lt1, 2);
            l0 = l0 * al0 + lt0;
            l1 = l1 * al1 + lt1;
            m0 = mn0;
            m1 = mn1;
            #pragma unroll
            for (int nt = 0; nt < 8; nt++) {
                o[nt][0] *= al0; o[nt][1] *= al0;
                o[nt][2] *= al1; o[nt][3] *= al1;
            }

            #pragma unroll
            for (int nt = 0; nt < 8; nt++) {
                Ps[r_q][nt * 8 + 2 * tig]         = to_tf32(s[nt][0]);
                Ps[r_q][nt * 8 + 2 * tig + 1]     = to_tf32(s[nt][1]);
                Ps[r_q + 8][nt * 8 + 2 * tig]     = to_tf32(s[nt][2]);
                Ps[r_q + 8][nt * 8 + 2 * tig + 1] = to_tf32(s[nt][3]);
            }
            __syncwarp();

            #pragma unroll
            for (int kk = 0; kk < 64; kk += 8) {
                float a[4];
                a[0] = Ps[r_q][kk + tig];
                a[1] = Ps[r_q + 8][kk + tig];
                a[2] = Ps[r_q][kk + tig + 4];
                a[3] = Ps[r_q + 8][kk + tig + 4];
                #pragma unroll
                for (int nt = 0; nt < 8; nt++) {
                    float bfr[2];
                    bfr[0] = Vs[kk + tig][nt * 8 + g];
                    bfr[1] = Vs[kk + tig + 4][nt * 8 + g];
                    mma_tf32(o[nt], a, bfr);
                }
            }
        }

        float inv0 = 1.f / l0;
        float inv1 = 1.f / l1;
        float* op0 = O + (size_t)(b * SS + i0 + r_q) * DD + h * DHH;
        float* op1 = op0 + 8 * DD;
        #pragma unroll
        for (int nt = 0; nt < 8; nt++) {
            *(float2*)(op0 + nt * 8 + 2 * tig) =
                make_float2(o[nt][0] * inv0, o[nt][1] * inv0);
            *(float2*)(op1 + nt * 8 + 2 * tig) =
                make_float2(o[nt][2] * inv1, o[nt][3] * inv1);
        }
    }
}

// ---------------------------------------------------------------------------
// GroupNorm stats, two-stage.
// Stage 1: grid (8, 32) — blockIdx.y = bh, blockIdx.x = partition.
// ---------------------------------------------------------------------------
__global__ __launch_bounds__(256) void gn_stats_part(const float* __restrict__ O,
                                                     double* __restrict__ part)
{
    const int bh = blockIdx.y;
    const int pp = blockIdx.x;
    const int b = bh >> 4;
    const int h = bh & 15;
    const float* base = O + ((size_t)b * SS * HH + h) * DHH;

    double sum = 0.0, sumsq = 0.0;
    // 32768 float4 groups per bh; 4096 per partition
    for (int i = threadIdx.x; i < 4096; i += 256) {
        int idx = pp * 4096 + i;
        int s_ = idx >> 4;
        int dg = (idx & 15) << 2;
        float4 v = *(const float4*)(base + (size_t)s_ * DD + dg);
        sum   += (double)v.x + (double)v.y + (double)v.z + (double)v.w;
        sumsq += (double)v.x * v.x + (double)v.y * v.y + (double)v.z * v.z + (double)v.w * v.w;
    }
    const int lane = threadIdx.x & 31;
    const int warp = threadIdx.x >> 5;
    #pragma unroll
    for (int off = 16; off > 0; off >>= 1) {
        sum   += __shfl_xor_sync(0xffffffffu, sum, off);
        sumsq += __shfl_xor_sync(0xffffffffu, sumsq, off);
    }
    __shared__ double ws[8], wq[8];
    if (lane == 0) { ws[warp] = sum; wq[warp] = sumsq; }
    __syncthreads();
    if (threadIdx.x == 0) {
        double ts = 0.0, tq = 0.0;
        #pragma unroll
        for (int i = 0; i < 8; i++) { ts += ws[i]; tq += wq[i]; }
        part[(bh * 8 + pp) * 2 + 0] = ts;
        part[(bh * 8 + pp) * 2 + 1] = tq;
    }
}

// Stage 2: one block, 256 threads; 8 threads per bh.
__global__ __launch_bounds__(256) void gn_stats_final(const double* __restrict__ part,
                                                      float* __restrict__ mean,
                                                      float* __restrict__ rstd)
{
    int tid = threadIdx.x;
    int bh = tid >> 3;
    int j  = tid & 7;
    double s = part[(bh * 8 + j) * 2 + 0];
    double q = part[(bh * 8 + j) * 2 + 1];
    #pragma unroll
    for (int off = 4; off > 0; off >>= 1) {
        s += __shfl_xor_sync(0xffffffffu, s, off);
        q += __shfl_xor_sync(0xffffffffu, q, off);
    }
    if (j == 0) {
        double n = (double)SS * DHH;
        double mu = s / n;
        double var = q / n - mu * mu;
        mean[bh] = (float)mu;
        rstd[bh] = (float)(1.0 / sqrt(var + (double)GN_EPS));
    }
}

// ---------------------------------------------------------------------------
extern "C" void kernel_launch(void* const* d_in, const int* in_sizes, int n_in,
                              void* d_out, int out_size) {
    const float* x   = (const float*)d_in[0];
    const float* Wq  = (const float*)d_in[1];
    const float* bq  = (const float*)d_in[2];
    const float* Wk  = (const float*)d_in[3];
    const float* bk  = (const float*)d_in[4];
    const float* Wv  = (const float*)d_in[5];
    const float* bv  = (const float*)d_in[6];
    const float* Wo  = (const float*)d_in[7];
    const float* bo  = (const float*)d_in[8];
    const float* lq1 = (const float*)d_in[9];
    const float* lk1 = (const float*)d_in[10];
    const float* lq2 = (const float*)d_in[11];
    const float* lk2 = (const float*)d_in[12];
    const float* gnw = (const float*)d_in[13];
    const float* gnb = (const float*)d_in[14];
    float* y = (float*)d_out;

    float *Qp, *Kp, *Vp, *AOp, *lamp, *meanp, *rstdp;
    double* partp;
    cudaGetSymbolAddress((void**)&Qp,    g_Q);
    cudaGetSymbolAddress((void**)&Kp,    g_K);
    cudaGetSymbolAddress((void**)&Vp,    g_V);
    cudaGetSymbolAddress((void**)&AOp,   g_AO);
    cudaGetSymbolAddress((void**)&lamp,  g_lam);
    cudaGetSymbolAddress((void**)&meanp, g_mean);
    cudaGetSymbolAddress((void**)&rstdp, g_rstd);
    cudaGetSymbolAddress((void**)&partp, g_part);

    static int attr_set = 0;
    if (!attr_set) {
        cudaFuncSetAttribute(flash_tf32, cudaFuncAttributeMaxDynamicSharedMemorySize,
                             FLASH_SMEM);
        attr_set = 1;
    }

    lambda_kernel<<<1, HH * 32>>>(lq1, lk1, lq2, lk2, lamp);

    gemm_qkv<<<dim3(24, 32), 256>>>(x, Wq, Wk, Wv, bq, bk, bv, Qp, Kp, Vp);

    flash_tf32<<<444, 128, FLASH_SMEM>>>(Qp, Kp, Vp, lamp, AOp);

    gn_stats_part<<<dim3(8, BB * HH), 256>>>(AOp, partp);
    gn_stats_final<<<1, 256>>>(partp, meanp, rstdp);

    gemm_o<<<dim3(8, 32), 256>>>(AOp, Wo, bo, y, meanp, rstdp, gnw, gnb);
}

// round 7
// speedup vs baseline: 1.3220x; 1.0593x over previous
#include <cuda_runtime.h>
#include <math.h>
#include <stdint.h>

// Problem constants
#define BB 2
#define SS 2048
#define DD 1024
#define HH 16
#define DHH 64
#define MM (BB*SS)          // 4096 rows
#define LAMBDA_INIT 0.8f
#define GN_EPS 1e-5f

// Scratch (device globals; no allocation allowed)
__device__ float g_Q[MM*DD];
__device__ float g_K[MM*DD];
__device__ float g_V[MM*DD];
__device__ float g_AO[MM*DD];   // attention output [B,S,H,DH]
__device__ float g_lam[HH];
__device__ float g_mean[BB*HH];
__device__ float g_rstd[BB*HH];
__device__ double g_part[BB*HH*16*2];   // [bh][part][{sum,sumsq}]

// ---------------------------------------------------------------------------
// helpers
// ---------------------------------------------------------------------------
__device__ __forceinline__ float to_tf32(float x) {
    unsigned u;
    asm("cvt.rna.tf32.f32 %0, %1;" : "=r"(u) : "f"(x));
    return __uint_as_float(u);
}
__device__ __forceinline__ float ex2(float x) {
    float r;
    asm("ex2.approx.ftz.f32 %0, %1;" : "=f"(r) : "f"(x));
    return r;
}

__device__ __forceinline__ void mma_tf32(float* c, const float* a, const float* b) {
    const unsigned* A = reinterpret_cast<const unsigned*>(a);
    const unsigned* B = reinterpret_cast<const unsigned*>(b);
    asm volatile(
        "mma.sync.aligned.m16n8k8.row.col.f32.tf32.tf32.f32 "
        "{%0,%1,%2,%3}, {%4,%5,%6,%7}, {%8,%9}, {%0,%1,%2,%3};\n"
        : "+f"(c[0]), "+f"(c[1]), "+f"(c[2]), "+f"(c[3])
        : "r"(A[0]), "r"(A[1]), "r"(A[2]), "r"(A[3]),
          "r"(B[0]), "r"(B[1]));
}

// ---------------------------------------------------------------------------
// lambda[h] = exp(<lq1,lk1>) - exp(<lq2,lk2>) + 0.8  (one warp/head)
// ---------------------------------------------------------------------------
__global__ void lambda_kernel(const float* __restrict__ lq1, const float* __restrict__ lk1,
                              const float* __restrict__ lq2, const float* __restrict__ lk2,
                              float* __restrict__ lam) {
    int h = threadIdx.x >> 5;
    int lane = threadIdx.x & 31;
    const float* a1 = lq1 + h * DHH;
    const float* b1 = lk1 + h * DHH;
    const float* a2 = lq2 + h * DHH;
    const float* b2 = lk2 + h * DHH;
    float s1 = a1[lane] * b1[lane] + a1[lane + 32] * b1[lane + 32];
    float s2 = a2[lane] * b2[lane] + a2[lane + 32] * b2[lane + 32];
    #pragma unroll
    for (int off = 16; off > 0; off >>= 1) {
        s1 += __shfl_xor_sync(0xffffffffu, s1, off);
        s2 += __shfl_xor_sync(0xffffffffu, s2, off);
    }
    if (lane == 0) lam[h] = expf(s1) - expf(s2) + LAMBDA_INIT;
}

// ---------------------------------------------------------------------------
// tf32 tensor-core GEMM core (round-2 proven inner loop).
// BM=128 BN=128 BK=16, 256 threads = 8 warps (2x4), warp tile 64x32,
// double-buffered smem.
// FUSE=1: A element -> ((A - mean[b,h]) * rstd[b,h]) * gnw[k] + gnb[k]
// ---------------------------------------------------------------------------
template<int FUSE>
__device__ __forceinline__ void gemm_core(
    float (*As)[128][20], float (*Bs)[16][136],
    const float* __restrict__ A, const float* __restrict__ B,
    const float* __restrict__ bias, float* __restrict__ C,
    int bm, int bn,
    const float* __restrict__ mean, const float* __restrict__ rstd,
    const float* __restrict__ gnw, const float* __restrict__ gnb)
{
    const int tid  = threadIdx.x;
    const int warp = tid >> 5;
    const int lane = tid & 31;
    const int g    = lane >> 2;
    const int tig  = lane & 3;
    const int wm   = warp >> 2;    // 0..1
    const int wn   = warp & 3;     // 0..3

    int arow[2], akc[2], bkr[2], bnc[2];
    #pragma unroll
    for (int i = 0; i < 2; i++) {
        int idx = tid + i * 256;
        arow[i] = idx >> 2;          // 0..127
        akc[i]  = (idx & 3) << 2;    // 0,4,8,12
        bkr[i]  = idx >> 5;          // 0..15
        bnc[i]  = (idx & 31) << 2;   // 0..124
    }

    float c[4][4][4];
    #pragma unroll
    for (int mt = 0; mt < 4; mt++)
        #pragma unroll
        for (int nt = 0; nt < 4; nt++)
            #pragma unroll
            for (int r = 0; r < 4; r++) c[mt][nt][r] = 0.f;

    float4 fa[2], fb[2];
    const int NT = DD / 16;

    auto do_fetch = [&](int kt) {
        #pragma unroll
        for (int i = 0; i < 2; i++) {
            fa[i] = *(const float4*)(A + (size_t)(bm + arow[i]) * DD + kt + akc[i]);
            if (FUSE) {
                int rowg = bm + arow[i];
                int bi   = rowg >> 11;          // row / 2048
                int k    = kt + akc[i];
                int hh   = k >> 6;
                float mu = mean[bi * HH + hh];
                float rs = rstd[bi * HH + hh];
                float4 w  = *(const float4*)(gnw + k);
                float4 gb = *(const float4*)(gnb + k);
                fa[i].x = (fa[i].x - mu) * rs * w.x + gb.x;
                fa[i].y = (fa[i].y - mu) * rs * w.y + gb.y;
                fa[i].z = (fa[i].z - mu) * rs * w.z + gb.z;
                fa[i].w = (fa[i].w - mu) * rs * w.w + gb.w;
            }
            fb[i] = *(const float4*)(B + (size_t)(kt + bkr[i]) * DD + bn + bnc[i]);
        }
    };
    auto do_store = [&](int buf) {
        #pragma unroll
        for (int i = 0; i < 2; i++) {
            As[buf][arow[i]][akc[i] + 0] = to_tf32(fa[i].x);
            As[buf][arow[i]][akc[i] + 1] = to_tf32(fa[i].y);
            As[buf][arow[i]][akc[i] + 2] = to_tf32(fa[i].z);
            As[buf][arow[i]][akc[i] + 3] = to_tf32(fa[i].w);
            Bs[buf][bkr[i]][bnc[i] + 0] = to_tf32(fb[i].x);
            Bs[buf][bkr[i]][bnc[i] + 1] = to_tf32(fb[i].y);
            Bs[buf][bkr[i]][bnc[i] + 2] = to_tf32(fb[i].z);
            Bs[buf][bkr[i]][bnc[i] + 3] = to_tf32(fb[i].w);
        }
    };

    do_fetch(0);
    do_store(0);
    __syncthreads();

    for (int t = 0; t < NT; t++) {
        int buf = t & 1;
        if (t + 1 < NT) do_fetch((t + 1) * 16);

        #pragma unroll
        for (int kk = 0; kk < 16; kk += 8) {
            float a[4][4], b[4][2];
            #pragma unroll
            for (int mt = 0; mt < 4; mt++) {
                int r0 = wm * 64 + mt * 16 + g;
                a[mt][0] = As[buf][r0][kk + tig];
                a[mt][1] = As[buf][r0 + 8][kk + tig];
                a[mt][2] = As[buf][r0][kk + tig + 4];
                a[mt][3] = As[buf][r0 + 8][kk + tig + 4];
            }
            #pragma unroll
            for (int nt = 0; nt < 4; nt++) {
                int cn = wn * 32 + nt * 8 + g;
                b[nt][0] = Bs[buf][kk + tig][cn];
                b[nt][1] = Bs[buf][kk + tig + 4][cn];
            }
            #pragma unroll
            for (int mt = 0; mt < 4; mt++)
                #pragma unroll
                for (int nt = 0; nt < 4; nt++)
                    mma_tf32(c[mt][nt], a[mt], b[nt]);
        }

        if (t + 1 < NT) do_store(buf ^ 1);
        __syncthreads();
    }

    // epilogue + bias
    #pragma unroll
    for (int mt = 0; mt < 4; mt++) {
        int row = bm + wm * 64 + mt * 16 + g;
        #pragma unroll
        for (int nt = 0; nt < 4; nt++) {
            int col = bn + wn * 32 + nt * 8 + 2 * tig;
            float2 bb = *(const float2*)(bias + col);
            *(float2*)(C + (size_t)row * DD + col) =
                make_float2(c[mt][nt][0] + bb.x, c[mt][nt][1] + bb.y);
            *(float2*)(C + (size_t)(row + 8) * DD + col) =
                make_float2(c[mt][nt][2] + bb.x, c[mt][nt][3] + bb.y);
        }
    }
}

// Fused Q/K/V projection: grid (24, 32); x-blocks 0-7 -> Q, 8-15 -> K, 16-23 -> V
__global__ __launch_bounds__(256, 2) void gemm_qkv(
    const float* __restrict__ x,
    const float* __restrict__ Wq, const float* __restrict__ Wk, const float* __restrict__ Wv,
    const float* __restrict__ bq, const float* __restrict__ bk, const float* __restrict__ bv,
    float* __restrict__ Q, float* __restrict__ K, float* __restrict__ V)
{
    __shared__ float As[2][128][20];
    __shared__ float Bs[2][16][136];

    int sel = blockIdx.x >> 3;
    const float* B    = (sel == 0) ? Wq : (sel == 1) ? Wk : Wv;
    const float* bias = (sel == 0) ? bq : (sel == 1) ? bk : bv;
    float*       C    = (sel == 0) ? Q  : (sel == 1) ? K  : V;
    int bn = (blockIdx.x & 7) * 128;
    int bm = blockIdx.y * 128;

    gemm_core<0>(As, Bs, x, B, bias, C, bm, bn, nullptr, nullptr, nullptr, nullptr);
}

// O projection with fused GroupNorm on the A operand
__global__ __launch_bounds__(256, 2) void gemm_o(
    const float* __restrict__ AO, const float* __restrict__ Wo,
    const float* __restrict__ bo, float* __restrict__ y,
    const float* __restrict__ mean, const float* __restrict__ rstd,
    const float* __restrict__ gnw, const float* __restrict__ gnb)
{
    __shared__ float As[2][128][20];
    __shared__ float Bs[2][16][136];
    gemm_core<1>(As, Bs, AO, Wo, bo, y,
                 blockIdx.y * 128, blockIdx.x * 128, mean, rstd, gnw, gnb);
}

// ---------------------------------------------------------------------------
// tf32 tensor-core flash attention — persistent, Q fragments in registers,
// log2-domain softmax. Br=Bc=64, DH=64. 128 threads = 4 warps.
// ---------------------------------------------------------------------------
#define FLASH_TILES (BB * HH * (SS / 64))   // 1024
#define FLASH_SMEM ((64*68 + 64*72 + 64*68) * 4)   // 53248 B

__global__ __launch_bounds__(128, 4) void flash_tf32(
    const float* __restrict__ Q, const float* __restrict__ K,
    const float* __restrict__ V, const float* __restrict__ lam,
    float* __restrict__ O)
{
    extern __shared__ float smf[];
    float (*Ks)[68] = (float(*)[68])(smf);
    float (*Vs)[72] = (float(*)[72])(smf + 64 * 68);
    float (*Ps)[68] = (float(*)[68])(smf + 64 * 68 + 64 * 72);

    const int tid  = threadIdx.x;
    const int warp = tid >> 5;
    const int lane = tid & 31;
    const int g    = lane >> 2;
    const int tig  = lane & 3;
    const int r_q  = (warp << 4) + g;

    for (int tile = blockIdx.x; tile < FLASH_TILES; tile += gridDim.x) {
        const int bh = tile >> 5;
        const int it = tile & 31;
        const int b  = bh >> 4;
        const int h  = bh & 15;
        const int i0 = it << 6;
        // DH^-0.5 * lambda * log2(e): log2-domain scores
        const float fac = 0.125f * lam[h] * 1.4426950408889634f;

        // ---- Q fragments -> registers (once per tile) ----
        float q[8][4];
        {
            const float* qp = Q + (size_t)(b * SS + i0 + r_q) * DD + h * DHH;
            #pragma unroll
            for (int kt = 0; kt < 8; kt++) {
                q[kt][0] = to_tf32(qp[kt * 8 + tig] * fac);
                q[kt][1] = to_tf32(qp[8 * DD + kt * 8 + tig] * fac);
                q[kt][2] = to_tf32(qp[kt * 8 + tig + 4] * fac);
                q[kt][3] = to_tf32(qp[8 * DD + kt * 8 + tig + 4] * fac);
            }
        }

        float o[8][4];
        #pragma unroll
        for (int nt = 0; nt < 8; nt++)
            #pragma unroll
            for (int r = 0; r < 4; r++) o[nt][r] = 0.f;
        float m0 = -INFINITY, m1 = -INFINITY, l0 = 0.f, l1 = 0.f;

        const float* kp0 = K + (size_t)b * SS * DD + h * DHH;
        const float* vp0 = V + (size_t)b * SS * DD + h * DHH;

        for (int jt = 0; jt < SS / 64; jt++) {
            __syncthreads();   // prev tile K/V reads done
            const float* kp = kp0 + (size_t)jt * 64 * DD;
            const float* vp = vp0 + (size_t)jt * 64 * DD;
            #pragma unroll
            for (int i = 0; i < 8; i++) {
                int idx = tid + i * 128;
                int r = idx >> 4, dg = (idx & 15) << 2;
                float4 kv = *(const float4*)(kp + (size_t)r * DD + dg);
                Ks[r][dg + 0] = to_tf32(kv.x);
                Ks[r][dg + 1] = to_tf32(kv.y);
                Ks[r][dg + 2] = to_tf32(kv.z);
                Ks[r][dg + 3] = to_tf32(kv.w);
                float4 vv = *(const float4*)(vp + (size_t)r * DD + dg);
                Vs[r][dg + 0] = to_tf32(vv.x);
                Vs[r][dg + 1] = to_tf32(vv.y);
                Vs[r][dg + 2] = to_tf32(vv.z);
                Vs[r][dg + 3] = to_tf32(vv.w);
            }
            __syncthreads();

            // ---- S = Q K^T (log2 domain) ----
            float s[8][4];
            #pragma unroll
            for (int nt = 0; nt < 8; nt++)
                #pragma unroll
                for (int r = 0; r < 4; r++) s[nt][r] = 0.f;

            #pragma unroll
            for (int kk = 0; kk < 8; kk++) {
                #pragma unroll
                for (int nt = 0; nt < 8; nt++) {
                    float bfr[2];
                    bfr[0] = Ks[nt * 8 + g][kk * 8 + tig];
                    bfr[1] = Ks[nt * 8 + g][kk * 8 + tig + 4];
                    mma_tf32(s[nt], q[kk], bfr);
                }
            }

            // ---- online softmax (exp2) ----
            float mx0 = -INFINITY, mx1 = -INFINITY;
            #pragma unroll
            for (int nt = 0; nt < 8; nt++) {
                mx0 = fmaxf(mx0, fmaxf(s[nt][0], s[nt][1]));
                mx1 = fmaxf(mx1, fmaxf(s[nt][2], s[nt][3]));
            }
            mx0 = fmaxf(mx0, __shfl_xor_sync(0xffffffffu, mx0, 1));
            mx0 = fmaxf(mx0, __shfl_xor_sync(0xffffffffu, mx0, 2));
            mx1 = fmaxf(mx1, __shfl_xor_sync(0xffffffffu, mx1, 1));
            mx1 = fmaxf(mx1, __shfl_xor_sync(0xffffffffu, mx1, 2));

            float mn0 = fmaxf(m0, mx0);
            float mn1 = fmaxf(m1, mx1);
            float al0 = ex2(m0 - mn0);
            float al1 = ex2(m1 - mn1);
            float lt0 = 0.f, lt1 = 0.f;
            #pragma unroll
            for (int nt = 0; nt < 8; nt++) {
                s[nt][0] = ex2(s[nt][0] - mn0); lt0 += s[nt][0];
                s[nt][1] = ex2(s[nt][1] - mn0); lt0 += s[nt][1];
                s[nt][2] = ex2(s[nt][2] - mn1); lt1 += s[nt][2];
                s[nt][3] = ex2(s[nt][3] - mn1); lt1 += s[nt][3];
            }
            lt0 += __shfl_xor_sync(0xffffffffu, lt0, 1);
            lt0 += __shfl_xor_sync(0xffffffffu, lt0, 2);
            lt1 += __shfl_xor_sync(0xffffffffu, lt1, 1);
            lt1 += __shfl_xor_sync(0xffffffffu, lt1, 2);
            l0 = l0 * al0 + lt0;
            l1 = l1 * al1 + lt1;
            m0 = mn0;
            m1 = mn1;
            #pragma unroll
            for (int nt = 0; nt < 8; nt++) {
                o[nt][0] *= al0; o[nt][1] *= al0;
                o[nt][2] *= al1; o[nt][3] *= al1;
            }

            // ---- P -> warp-private smem rows ----
            #pragma unroll
            for (int nt = 0; nt < 8; nt++) {
                Ps[r_q][nt * 8 + 2 * tig]         = to_tf32(s[nt][0]);
                Ps[r_q][nt * 8 + 2 * tig + 1]     = to_tf32(s[nt][1]);
                Ps[r_q + 8][nt * 8 + 2 * tig]     = to_tf32(s[nt][2]);
                Ps[r_q + 8][nt * 8 + 2 * tig + 1] = to_tf32(s[nt][3]);
            }
            __syncwarp();

            // ---- O += P @ V ----
            #pragma unroll
            for (int kk = 0; kk < 64; kk += 8) {
                float a[4];
                a[0] = Ps[r_q][kk + tig];
                a[1] = Ps[r_q + 8][kk + tig];
                a[2] = Ps[r_q][kk + tig + 4];
                a[3] = Ps[r_q + 8][kk + tig + 4];
                #pragma unroll
                for (int nt = 0; nt < 8; nt++) {
                    float bfr[2];
                    bfr[0] = Vs[kk + tig][nt * 8 + g];
                    bfr[1] = Vs[kk + tig + 4][nt * 8 + g];
                    mma_tf32(o[nt], a, bfr);
                }
            }
        }

        float inv0 = 1.f / l0;
        float inv1 = 1.f / l1;
        float* op0 = O + (size_t)(b * SS + i0 + r_q) * DD + h * DHH;
        float* op1 = op0 + 8 * DD;
        #pragma unroll
        for (int nt = 0; nt < 8; nt++) {
            *(float2*)(op0 + nt * 8 + 2 * tig) =
                make_float2(o[nt][0] * inv0, o[nt][1] * inv0);
            *(float2*)(op1 + nt * 8 + 2 * tig) =
                make_float2(o[nt][2] * inv1, o[nt][3] * inv1);
        }
    }
}

// ---------------------------------------------------------------------------
// GroupNorm stats, two-stage. Stage 1: grid (16, 32), fp32 thread accum.
// ---------------------------------------------------------------------------
__global__ __launch_bounds__(256) void gn_stats_part(const float* __restrict__ O,
                                                     double* __restrict__ part)
{
    const int bh = blockIdx.y;
    const int pp = blockIdx.x;
    const int b = bh >> 4;
    const int h = bh & 15;
    const float* base = O + ((size_t)b * SS * HH + h) * DHH;

    float sum = 0.f, sumsq = 0.f;
    // 32768 float4 groups per bh; 2048 per partition
    for (int i = threadIdx.x; i < 2048; i += 256) {
        int idx = pp * 2048 + i;
        int s_ = idx >> 4;
        int dg = (idx & 15) << 2;
        float4 v = *(const float4*)(base + (size_t)s_ * DD + dg);
        sum   += v.x + v.y + v.z + v.w;
        sumsq += v.x * v.x + v.y * v.y + v.z * v.z + v.w * v.w;
    }
    double ds = (double)sum, dq = (double)sumsq;
    const int lane = threadIdx.x & 31;
    const int warp = threadIdx.x >> 5;
    #pragma unroll
    for (int off = 16; off > 0; off >>= 1) {
        ds += __shfl_xor_sync(0xffffffffu, ds, off);
        dq += __shfl_xor_sync(0xffffffffu, dq, off);
    }
    __shared__ double ws[8], wq[8];
    if (lane == 0) { ws[warp] = ds; wq[warp] = dq; }
    __syncthreads();
    if (threadIdx.x == 0) {
        double ts = 0.0, tq = 0.0;
        #pragma unroll
        for (int i = 0; i < 8; i++) { ts += ws[i]; tq += wq[i]; }
        part[(bh * 16 + pp) * 2 + 0] = ts;
        part[(bh * 16 + pp) * 2 + 1] = tq;
    }
}

// Stage 2: one block, 512 threads; 16 threads per bh.
__global__ __launch_bounds__(512) void gn_stats_final(const double* __restrict__ part,
                                                      float* __restrict__ mean,
                                                      float* __restrict__ rstd)
{
    int tid = threadIdx.x;
    int bh = tid >> 4;
    int j  = tid & 15;
    double s = part[(bh * 16 + j) * 2 + 0];
    double q = part[(bh * 16 + j) * 2 + 1];
    #pragma unroll
    for (int off = 8; off > 0; off >>= 1) {
        s += __shfl_xor_sync(0xffffffffu, s, off);
        q += __shfl_xor_sync(0xffffffffu, q, off);
    }
    if (j == 0) {
        double n = (double)SS * DHH;
        double mu = s / n;
        double var = q / n - mu * mu;
        mean[bh] = (float)mu;
        rstd[bh] = (float)(1.0 / sqrt(var + (double)GN_EPS));
    }
}

// ---------------------------------------------------------------------------
extern "C" void kernel_launch(void* const* d_in, const int* in_sizes, int n_in,
                              void* d_out, int out_size) {
    const float* x   = (const float*)d_in[0];
    const float* Wq  = (const float*)d_in[1];
    const float* bq  = (const float*)d_in[2];
    const float* Wk  = (const float*)d_in[3];
    const float* bk  = (const float*)d_in[4];
    const float* Wv  = (const float*)d_in[5];
    const float* bv  = (const float*)d_in[6];
    const float* Wo  = (const float*)d_in[7];
    const float* bo  = (const float*)d_in[8];
    const float* lq1 = (const float*)d_in[9];
    const float* lk1 = (const float*)d_in[10];
    const float* lq2 = (const float*)d_in[11];
    const float* lk2 = (const float*)d_in[12];
    const float* gnw = (const float*)d_in[13];
    const float* gnb = (const float*)d_in[14];
    float* y = (float*)d_out;

    float *Qp, *Kp, *Vp, *AOp, *lamp, *meanp, *rstdp;
    double* partp;
    cudaGetSymbolAddress((void**)&Qp,    g_Q);
    cudaGetSymbolAddress((void**)&Kp,    g_K);
    cudaGetSymbolAddress((void**)&Vp,    g_V);
    cudaGetSymbolAddress((void**)&AOp,   g_AO);
    cudaGetSymbolAddress((void**)&lamp,  g_lam);
    cudaGetSymbolAddress((void**)&meanp, g_mean);
    cudaGetSymbolAddress((void**)&rstdp, g_rstd);
    cudaGetSymbolAddress((void**)&partp, g_part);

    static int attr_set = 0;
    if (!attr_set) {
        cudaFuncSetAttribute(flash_tf32, cudaFuncAttributeMaxDynamicSharedMemorySize,
                             FLASH_SMEM);
        attr_set = 1;
    }

    lambda_kernel<<<1, HH * 32>>>(lq1, lk1, lq2, lk2, lamp);

    gemm_qkv<<<dim3(24, 32), 256>>>(x, Wq, Wk, Wv, bq, bk, bv, Qp, Kp, Vp);

    flash_tf32<<<592, 128, FLASH_SMEM>>>(Qp, Kp, Vp, lamp, AOp);

    gn_stats_part<<<dim3(16, BB * HH), 256>>>(AOp, partp);
    gn_stats_final<<<1, 512>>>(partp, meanp, rstdp);

    gemm_o<<<dim3(8, 32), 256>>>(AOp, Wo, bo, y, meanp, rstdp, gnw, gnb);
}

// round 8
// speedup vs baseline: 1.4546x; 1.1003x over previous
#include <cuda_runtime.h>
#include <math.h>
#include <stdint.h>

// Problem constants
#define BB 2
#define SS 2048
#define DD 1024
#define HH 16
#define DHH 64
#define MM (BB*SS)          // 4096 rows
#define LAMBDA_INIT 0.8f
#define GN_EPS 1e-5f

// Scratch (device globals; no allocation allowed)
__device__ float g_Q[MM*DD];
__device__ float g_K[MM*DD];
__device__ float g_V[MM*DD];
__device__ float g_AO[MM*DD];   // attention output [B,S,H,DH]
__device__ float g_lam[HH];
__device__ float g_mean[BB*HH];
__device__ float g_rstd[BB*HH];
__device__ double g_part[BB*HH*16*2];   // [bh][part][{sum,sumsq}]

// ---------------------------------------------------------------------------
// helpers
// ---------------------------------------------------------------------------
__device__ __forceinline__ float to_tf32(float x) {
    unsigned u;
    asm("cvt.rna.tf32.f32 %0, %1;" : "=r"(u) : "f"(x));
    return __uint_as_float(u);
}
__device__ __forceinline__ float ex2(float x) {
    float r;
    asm("ex2.approx.ftz.f32 %0, %1;" : "=f"(r) : "f"(x));
    return r;
}
__device__ __forceinline__ uint32_t smem_u32(const void* p) {
    uint32_t a;
    asm("{ .reg .u64 t; cvta.to.shared.u64 t, %1; cvt.u32.u64 %0, t; }" : "=r"(a) : "l"(p));
    return a;
}
__device__ __forceinline__ void cp_async16(uint32_t dst, const void* src) {
    asm volatile("cp.async.cg.shared.global [%0], [%1], 16;" :: "r"(dst), "l"(src));
}
#define CP_COMMIT() asm volatile("cp.async.commit_group;" ::: "memory")
#define CP_WAIT(n)  asm volatile("cp.async.wait_group %0;" :: "n"(n) : "memory")

__device__ __forceinline__ void mma_tf32(float* c, const float* a, const float* b) {
    const unsigned* A = reinterpret_cast<const unsigned*>(a);
    const unsigned* B = reinterpret_cast<const unsigned*>(b);
    asm volatile(
        "mma.sync.aligned.m16n8k8.row.col.f32.tf32.tf32.f32 "
        "{%0,%1,%2,%3}, {%4,%5,%6,%7}, {%8,%9}, {%0,%1,%2,%3};\n"
        : "+f"(c[0]), "+f"(c[1]), "+f"(c[2]), "+f"(c[3])
        : "r"(A[0]), "r"(A[1]), "r"(A[2]), "r"(A[3]),
          "r"(B[0]), "r"(B[1]));
}

// ---------------------------------------------------------------------------
// lambda[h] = exp(<lq1,lk1>) - exp(<lq2,lk2>) + 0.8  (one warp/head)
// ---------------------------------------------------------------------------
__global__ void lambda_kernel(const float* __restrict__ lq1, const float* __restrict__ lk1,
                              const float* __restrict__ lq2, const float* __restrict__ lk2,
                              float* __restrict__ lam) {
    int h = threadIdx.x >> 5;
    int lane = threadIdx.x & 31;
    const float* a1 = lq1 + h * DHH;
    const float* b1 = lk1 + h * DHH;
    const float* a2 = lq2 + h * DHH;
    const float* b2 = lk2 + h * DHH;
    float s1 = a1[lane] * b1[lane] + a1[lane + 32] * b1[lane + 32];
    float s2 = a2[lane] * b2[lane] + a2[lane + 32] * b2[lane + 32];
    #pragma unroll
    for (int off = 16; off > 0; off >>= 1) {
        s1 += __shfl_xor_sync(0xffffffffu, s1, off);
        s2 += __shfl_xor_sync(0xffffffffu, s2, off);
    }
    if (lane == 0) lam[h] = expf(s1) - expf(s2) + LAMBDA_INIT;
}

// ---------------------------------------------------------------------------
// tf32 tensor-core GEMM core (proven inner loop, unchanged).
// BM=128 BN=128 BK=16, 256 threads = 8 warps (2x4), warp tile 64x32.
// FUSE=1: A element -> ((A - mean[b,h]) * rstd[b,h]) * gnw[k] + gnb[k]
// ---------------------------------------------------------------------------
template<int FUSE>
__device__ __forceinline__ void gemm_core(
    float (*As)[128][20], float (*Bs)[16][136],
    const float* __restrict__ A, const float* __restrict__ B,
    const float* __restrict__ bias, float* __restrict__ C,
    int bm, int bn,
    const float* __restrict__ mean, const float* __restrict__ rstd,
    const float* __restrict__ gnw, const float* __restrict__ gnb)
{
    const int tid  = threadIdx.x;
    const int warp = tid >> 5;
    const int lane = tid & 31;
    const int g    = lane >> 2;
    const int tig  = lane & 3;
    const int wm   = warp >> 2;    // 0..1
    const int wn   = warp & 3;     // 0..3

    int arow[2], akc[2], bkr[2], bnc[2];
    #pragma unroll
    for (int i = 0; i < 2; i++) {
        int idx = tid + i * 256;
        arow[i] = idx >> 2;          // 0..127
        akc[i]  = (idx & 3) << 2;    // 0,4,8,12
        bkr[i]  = idx >> 5;          // 0..15
        bnc[i]  = (idx & 31) << 2;   // 0..124
    }

    float c[4][4][4];
    #pragma unroll
    for (int mt = 0; mt < 4; mt++)
        #pragma unroll
        for (int nt = 0; nt < 4; nt++)
            #pragma unroll
            for (int r = 0; r < 4; r++) c[mt][nt][r] = 0.f;

    float4 fa[2], fb[2];
    const int NT = DD / 16;

    auto do_fetch = [&](int kt) {
        #pragma unroll
        for (int i = 0; i < 2; i++) {
            fa[i] = *(const float4*)(A + (size_t)(bm + arow[i]) * DD + kt + akc[i]);
            if (FUSE) {
                int rowg = bm + arow[i];
                int bi   = rowg >> 11;          // row / 2048
                int k    = kt + akc[i];
                int hh   = k >> 6;
                float mu = mean[bi * HH + hh];
                float rs = rstd[bi * HH + hh];
                float4 w  = *(const float4*)(gnw + k);
                float4 gb = *(const float4*)(gnb + k);
                fa[i].x = (fa[i].x - mu) * rs * w.x + gb.x;
                fa[i].y = (fa[i].y - mu) * rs * w.y + gb.y;
                fa[i].z = (fa[i].z - mu) * rs * w.z + gb.z;
                fa[i].w = (fa[i].w - mu) * rs * w.w + gb.w;
            }
            fb[i] = *(const float4*)(B + (size_t)(kt + bkr[i]) * DD + bn + bnc[i]);
        }
    };
    auto do_store = [&](int buf) {
        #pragma unroll
        for (int i = 0; i < 2; i++) {
            As[buf][arow[i]][akc[i] + 0] = to_tf32(fa[i].x);
            As[buf][arow[i]][akc[i] + 1] = to_tf32(fa[i].y);
            As[buf][arow[i]][akc[i] + 2] = to_tf32(fa[i].z);
            As[buf][arow[i]][akc[i] + 3] = to_tf32(fa[i].w);
            Bs[buf][bkr[i]][bnc[i] + 0] = to_tf32(fb[i].x);
            Bs[buf][bkr[i]][bnc[i] + 1] = to_tf32(fb[i].y);
            Bs[buf][bkr[i]][bnc[i] + 2] = to_tf32(fb[i].z);
            Bs[buf][bkr[i]][bnc[i] + 3] = to_tf32(fb[i].w);
        }
    };

    do_fetch(0);
    do_store(0);
    __syncthreads();

    for (int t = 0; t < NT; t++) {
        int buf = t & 1;
        if (t + 1 < NT) do_fetch((t + 1) * 16);

        #pragma unroll
        for (int kk = 0; kk < 16; kk += 8) {
            float a[4][4], b[4][2];
            #pragma unroll
            for (int mt = 0; mt < 4; mt++) {
                int r0 = wm * 64 + mt * 16 + g;
                a[mt][0] = As[buf][r0][kk + tig];
                a[mt][1] = As[buf][r0 + 8][kk + tig];
                a[mt][2] = As[buf][r0][kk + tig + 4];
                a[mt][3] = As[buf][r0 + 8][kk + tig + 4];
            }
            #pragma unroll
            for (int nt = 0; nt < 4; nt++) {
                int cn = wn * 32 + nt * 8 + g;
                b[nt][0] = Bs[buf][kk + tig][cn];
                b[nt][1] = Bs[buf][kk + tig + 4][cn];
            }
            #pragma unroll
            for (int mt = 0; mt < 4; mt++)
                #pragma unroll
                for (int nt = 0; nt < 4; nt++)
                    mma_tf32(c[mt][nt], a[mt], b[nt]);
        }

        if (t + 1 < NT) do_store(buf ^ 1);
        __syncthreads();
    }

    // epilogue + bias
    #pragma unroll
    for (int mt = 0; mt < 4; mt++) {
        int row = bm + wm * 64 + mt * 16 + g;
        #pragma unroll
        for (int nt = 0; nt < 4; nt++) {
            int col = bn + wn * 32 + nt * 8 + 2 * tig;
            float2 bb = *(const float2*)(bias + col);
            *(float2*)(C + (size_t)row * DD + col) =
                make_float2(c[mt][nt][0] + bb.x, c[mt][nt][1] + bb.y);
            *(float2*)(C + (size_t)(row + 8) * DD + col) =
                make_float2(c[mt][nt][2] + bb.x, c[mt][nt][3] + bb.y);
        }
    }
}

// Fused Q/K/V projection: grid (24, 32); x-blocks 0-7 -> Q, 8-15 -> K, 16-23 -> V
__global__ __launch_bounds__(256, 2) void gemm_qkv(
    const float* __restrict__ x,
    const float* __restrict__ Wq, const float* __restrict__ Wk, const float* __restrict__ Wv,
    const float* __restrict__ bq, const float* __restrict__ bk, const float* __restrict__ bv,
    float* __restrict__ Q, float* __restrict__ K, float* __restrict__ V)
{
    __shared__ float As[2][128][20];
    __shared__ float Bs[2][16][136];

    int sel = blockIdx.x >> 3;
    const float* B    = (sel == 0) ? Wq : (sel == 1) ? Wk : Wv;
    const float* bias = (sel == 0) ? bq : (sel == 1) ? bk : bv;
    float*       C    = (sel == 0) ? Q  : (sel == 1) ? K  : V;
    int bn = (blockIdx.x & 7) * 128;
    int bm = blockIdx.y * 128;

    gemm_core<0>(As, Bs, x, B, bias, C, bm, bn, nullptr, nullptr, nullptr, nullptr);
}

// O projection with fused GroupNorm on the A operand
__global__ __launch_bounds__(256, 2) void gemm_o(
    const float* __restrict__ AO, const float* __restrict__ Wo,
    const float* __restrict__ bo, float* __restrict__ y,
    const float* __restrict__ mean, const float* __restrict__ rstd,
    const float* __restrict__ gnw, const float* __restrict__ gnb)
{
    __shared__ float As[2][128][20];
    __shared__ float Bs[2][16][136];
    gemm_core<1>(As, Bs, AO, Wo, bo, y,
                 blockIdx.y * 128, blockIdx.x * 128, mean, rstd, gnw, gnb);
}

// ---------------------------------------------------------------------------
// tf32 flash attention — persistent, Q-in-regs, log2 softmax,
// cp.async phase-pipelined K/V (K refills during PV, V refills during QK).
// Br=Bc=64, DH=64, 128 threads = 4 warps.
// ---------------------------------------------------------------------------
#define FLASH_TILES (BB * HH * (SS / 64))   // 1024
#define NJ (SS / 64)                        // 32
#define FLASH_SMEM ((64*68 + 64*72 + 64*68) * 4)   // Ks, Vs, Ps = 53248 B

__global__ __launch_bounds__(128, 4) void flash_tf32(
    const float* __restrict__ Q, const float* __restrict__ K,
    const float* __restrict__ V, const float* __restrict__ lam,
    float* __restrict__ O)
{
    extern __shared__ float smf[];
    float (*Ks)[68] = (float(*)[68])(smf);
    float (*Vs)[72] = (float(*)[72])(smf + 64 * 68);
    float (*Ps)[68] = (float(*)[68])(smf + 64 * 68 + 64 * 72);

    const int tid  = threadIdx.x;
    const int warp = tid >> 5;
    const int lane = tid & 31;
    const int g    = lane >> 2;
    const int tig  = lane & 3;
    const int r_q  = (warp << 4) + g;

    const uint32_t ks_base = smem_u32(&Ks[0][0]);
    const uint32_t vs_base = smem_u32(&Vs[0][0]);

    // per-thread fill slots: 8 x 16B covering the 64x64 tile
    int fr[8], fd[8];
    #pragma unroll
    for (int i = 0; i < 8; i++) {
        int idx = tid + i * 128;
        fr[i] = idx >> 4;
        fd[i] = (idx & 15) << 2;
    }

    for (int tile = blockIdx.x; tile < FLASH_TILES; tile += gridDim.x) {
        const int bh = tile >> 5;
        const int it = tile & 31;
        const int b  = bh >> 4;
        const int h  = bh & 15;
        const int i0 = it << 6;
        const float fac = 0.125f * lam[h] * 1.4426950408889634f;  // lambda*scale*log2e

        const float* kp0 = K + (size_t)b * SS * DD + h * DHH;
        const float* vp0 = V + (size_t)b * SS * DD + h * DHH;

        // ---- prologue: issue K(0), V(0) ----
        #pragma unroll
        for (int i = 0; i < 8; i++)
            cp_async16(ks_base + (uint32_t)(fr[i] * 68 + fd[i]) * 4,
                       kp0 + (size_t)fr[i] * DD + fd[i]);
        CP_COMMIT();
        #pragma unroll
        for (int i = 0; i < 8; i++)
            cp_async16(vs_base + (uint32_t)(fr[i] * 72 + fd[i]) * 4,
                       vp0 + (size_t)fr[i] * DD + fd[i]);
        CP_COMMIT();

        // ---- Q fragments -> registers (overlaps with cp.async) ----
        float q[8][4];
        {
            const float* qp = Q + (size_t)(b * SS + i0 + r_q) * DD + h * DHH;
            #pragma unroll
            for (int kt = 0; kt < 8; kt++) {
                q[kt][0] = to_tf32(qp[kt * 8 + tig] * fac);
                q[kt][1] = to_tf32(qp[8 * DD + kt * 8 + tig] * fac);
                q[kt][2] = to_tf32(qp[kt * 8 + tig + 4] * fac);
                q[kt][3] = to_tf32(qp[8 * DD + kt * 8 + tig + 4] * fac);
            }
        }

        float o[8][4];
        #pragma unroll
        for (int nt = 0; nt < 8; nt++)
            #pragma unroll
            for (int r = 0; r < 4; r++) o[nt][r] = 0.f;
        float m0 = -INFINITY, m1 = -INFINITY, l0 = 0.f, l1 = 0.f;

        for (int jt = 0; jt < NJ; jt++) {
            // ---- K(jt) ready? (pending: [K(jt), V(jt)]) ----
            if (jt == NJ - 1) { CP_WAIT(0); } else { CP_WAIT(1); }
            __syncthreads();

            // ---- S = Q K^T ----
            float s[8][4];
            #pragma unroll
            for (int nt = 0; nt < 8; nt++)
                #pragma unroll
                for (int r = 0; r < 4; r++) s[nt][r] = 0.f;

            #pragma unroll
            for (int kk = 0; kk < 8; kk++) {
                #pragma unroll
                for (int nt = 0; nt < 8; nt++) {
                    float bfr[2];
                    bfr[0] = Ks[nt * 8 + g][kk * 8 + tig];
                    bfr[1] = Ks[nt * 8 + g][kk * 8 + tig + 4];
                    mma_tf32(s[nt], q[kk], bfr);
                }
            }
            __syncthreads();   // all warps done reading Ks

            // ---- refill K for jt+1 (lands during PV phase) ----
            if (jt + 1 < NJ) {
                const float* kp = kp0 + (size_t)(jt + 1) * 64 * DD;
                #pragma unroll
                for (int i = 0; i < 8; i++)
                    cp_async16(ks_base + (uint32_t)(fr[i] * 68 + fd[i]) * 4,
                               kp + (size_t)fr[i] * DD + fd[i]);
                CP_COMMIT();
            }

            // ---- online softmax (log2 domain) ----
            float mx0 = -INFINITY, mx1 = -INFINITY;
            #pragma unroll
            for (int nt = 0; nt < 8; nt++) {
                mx0 = fmaxf(mx0, fmaxf(s[nt][0], s[nt][1]));
                mx1 = fmaxf(mx1, fmaxf(s[nt][2], s[nt][3]));
            }
            mx0 = fmaxf(mx0, __shfl_xor_sync(0xffffffffu, mx0, 1));
            mx0 = fmaxf(mx0, __shfl_xor_sync(0xffffffffu, mx0, 2));
            mx1 = fmaxf(mx1, __shfl_xor_sync(0xffffffffu, mx1, 1));
            mx1 = fmaxf(mx1, __shfl_xor_sync(0xffffffffu, mx1, 2));

            float mn0 = fmaxf(m0, mx0);
            float mn1 = fmaxf(m1, mx1);
            float al0 = ex2(m0 - mn0);
            float al1 = ex2(m1 - mn1);
            float lt0 = 0.f, lt1 = 0.f;
            #pragma unroll
            for (int nt = 0; nt < 8; nt++) {
                s[nt][0] = ex2(s[nt][0] - mn0); lt0 += s[nt][0];
                s[nt][1] = ex2(s[nt][1] - mn0); lt0 += s[nt][1];
                s[nt][2] = ex2(s[nt][2] - mn1); lt1 += s[nt][2];
                s[nt][3] = ex2(s[nt][3] - mn1); lt1 += s[nt][3];
            }
            lt0 += __shfl_xor_sync(0xffffffffu, lt0, 1);
            lt0 += __shfl_xor_sync(0xffffffffu, lt0, 2);
            lt1 += __shfl_xor_sync(0xffffffffu, lt1, 1);
            lt1 += __shfl_xor_sync(0xffffffffu, lt1, 2);
            l0 = l0 * al0 + lt0;
            l1 = l1 * al1 + lt1;
            m0 = mn0;
            m1 = mn1;
            #pragma unroll
            for (int nt = 0; nt < 8; nt++) {
                o[nt][0] *= al0; o[nt][1] *= al0;
                o[nt][2] *= al1; o[nt][3] *= al1;
            }

            // ---- P -> warp-private smem rows ----
            #pragma unroll
            for (int nt = 0; nt < 8; nt++) {
                Ps[r_q][nt * 8 + 2 * tig]         = to_tf32(s[nt][0]);
                Ps[r_q][nt * 8 + 2 * tig + 1]     = to_tf32(s[nt][1]);
                Ps[r_q + 8][nt * 8 + 2 * tig]     = to_tf32(s[nt][2]);
                Ps[r_q + 8][nt * 8 + 2 * tig + 1] = to_tf32(s[nt][3]);
            }
            __syncwarp();

            // ---- V(jt) ready? (pending: [V(jt), K(jt+1)] or [V(jt)]) ----
            if (jt == NJ - 1) { CP_WAIT(0); } else { CP_WAIT(1); }
            __syncthreads();

            // ---- O += P @ V ----
            #pragma unroll
            for (int kk = 0; kk < 64; kk += 8) {
                float a[4];
                a[0] = Ps[r_q][kk + tig];
                a[1] = Ps[r_q + 8][kk + tig];
                a[2] = Ps[r_q][kk + tig + 4];
                a[3] = Ps[r_q + 8][kk + tig + 4];
                #pragma unroll
                for (int nt = 0; nt < 8; nt++) {
                    float bfr[2];
                    bfr[0] = Vs[kk + tig][nt * 8 + g];
                    bfr[1] = Vs[kk + tig + 4][nt * 8 + g];
                    mma_tf32(o[nt], a, bfr);
                }
            }
            __syncthreads();   // all warps done reading Vs

            // ---- refill V for jt+1 (lands during next QK phase) ----
            if (jt + 1 < NJ) {
                const float* vp = vp0 + (size_t)(jt + 1) * 64 * DD;
                #pragma unroll
                for (int i = 0; i < 8; i++)
                    cp_async16(vs_base + (uint32_t)(fr[i] * 72 + fd[i]) * 4,
                               vp + (size_t)fr[i] * DD + fd[i]);
                CP_COMMIT();
            }
        }

        float inv0 = 1.f / l0;
        float inv1 = 1.f / l1;
        float* op0 = O + (size_t)(b * SS + i0 + r_q) * DD + h * DHH;
        float* op1 = op0 + 8 * DD;
        #pragma unroll
        for (int nt = 0; nt < 8; nt++) {
            *(float2*)(op0 + nt * 8 + 2 * tig) =
                make_float2(o[nt][0] * inv0, o[nt][1] * inv0);
            *(float2*)(op1 + nt * 8 + 2 * tig) =
                make_float2(o[nt][2] * inv1, o[nt][3] * inv1);
        }
    }
}

// ---------------------------------------------------------------------------
// GroupNorm stats, two-stage. Stage 1: grid (16, 32), fp32 thread accum.
// ---------------------------------------------------------------------------
__global__ __launch_bounds__(256) void gn_stats_part(const float* __restrict__ O,
                                                     double* __restrict__ part)
{
    const int bh = blockIdx.y;
    const int pp = blockIdx.x;
    const int b = bh >> 4;
    const int h = bh & 15;
    const float* base = O + ((size_t)b * SS * HH + h) * DHH;

    float sum = 0.f, sumsq = 0.f;
    for (int i = threadIdx.x; i < 2048; i += 256) {
        int idx = pp * 2048 + i;
        int s_ = idx >> 4;
        int dg = (idx & 15) << 2;
        float4 v = *(const float4*)(base + (size_t)s_ * DD + dg);
        sum   += v.x + v.y + v.z + v.w;
        sumsq += v.x * v.x + v.y * v.y + v.z * v.z + v.w * v.w;
    }
    double ds = (double)sum, dq = (double)sumsq;
    const int lane = threadIdx.x & 31;
    const int warp = threadIdx.x >> 5;
    #pragma unroll
    for (int off = 16; off > 0; off >>= 1) {
        ds += __shfl_xor_sync(0xffffffffu, ds, off);
        dq += __shfl_xor_sync(0xffffffffu, dq, off);
    }
    __shared__ double ws[8], wq[8];
    if (lane == 0) { ws[warp] = ds; wq[warp] = dq; }
    __syncthreads();
    if (threadIdx.x == 0) {
        double ts = 0.0, tq = 0.0;
        #pragma unroll
        for (int i = 0; i < 8; i++) { ts += ws[i]; tq += wq[i]; }
        part[(bh * 16 + pp) * 2 + 0] = ts;
        part[(bh * 16 + pp) * 2 + 1] = tq;
    }
}

// Stage 2: one block, 512 threads; 16 threads per bh.
__global__ __launch_bounds__(512) void gn_stats_final(const double* __restrict__ part,
                                                      float* __restrict__ mean,
                                                      float* __restrict__ rstd)
{
    int tid = threadIdx.x;
    int bh = tid >> 4;
    int j  = tid & 15;
    double s = part[(bh * 16 + j) * 2 + 0];
    double q = part[(bh * 16 + j) * 2 + 1];
    #pragma unroll
    for (int off = 8; off > 0; off >>= 1) {
        s += __shfl_xor_sync(0xffffffffu, s, off);
        q += __shfl_xor_sync(0xffffffffu, q, off);
    }
    if (j == 0) {
        double n = (double)SS * DHH;
        double mu = s / n;
        double var = q / n - mu * mu;
        mean[bh] = (float)mu;
        rstd[bh] = (float)(1.0 / sqrt(var + (double)GN_EPS));
    }
}

// ---------------------------------------------------------------------------
extern "C" void kernel_launch(void* const* d_in, const int* in_sizes, int n_in,
                              void* d_out, int out_size) {
    const float* x   = (const float*)d_in[0];
    const float* Wq  = (const float*)d_in[1];
    const float* bq  = (const float*)d_in[2];
    const float* Wk  = (const float*)d_in[3];
    const float* bk  = (const float*)d_in[4];
    const float* Wv  = (const float*)d_in[5];
    const float* bv  = (const float*)d_in[6];
    const float* Wo  = (const float*)d_in[7];
    const float* bo  = (const float*)d_in[8];
    const float* lq1 = (const float*)d_in[9];
    const float* lk1 = (const float*)d_in[10];
    const float* lq2 = (const float*)d_in[11];
    const float* lk2 = (const float*)d_in[12];
    const float* gnw = (const float*)d_in[13];
    const float* gnb = (const float*)d_in[14];
    float* y = (float*)d_out;

    float *Qp, *Kp, *Vp, *AOp, *lamp, *meanp, *rstdp;
    double* partp;
    cudaGetSymbolAddress((void**)&Qp,    g_Q);
    cudaGetSymbolAddress((void**)&Kp,    g_K);
    cudaGetSymbolAddress((void**)&Vp,    g_V);
    cudaGetSymbolAddress((void**)&AOp,   g_AO);
    cudaGetSymbolAddress((void**)&lamp,  g_lam);
    cudaGetSymbolAddress((void**)&meanp, g_mean);
    cudaGetSymbolAddress((void**)&rstdp, g_rstd);
    cudaGetSymbolAddress((void**)&partp, g_part);

    static int attr_set = 0;
    if (!attr_set) {
        cudaFuncSetAttribute(flash_tf32, cudaFuncAttributeMaxDynamicSharedMemorySize,
                             FLASH_SMEM);
        attr_set = 1;
    }

    lambda_kernel<<<1, HH * 32>>>(lq1, lk1, lq2, lk2, lamp);

    gemm_qkv<<<dim3(24, 32), 256>>>(x, Wq, Wk, Wv, bq, bk, bv, Qp, Kp, Vp);

    flash_tf32<<<592, 128, FLASH_SMEM>>>(Qp, Kp, Vp, lamp, AOp);

    gn_stats_part<<<dim3(16, BB * HH), 256>>>(AOp, partp);
    gn_stats_final<<<1, 512>>>(partp, meanp, rstdp);

    gemm_o<<<dim3(8, 32), 256>>>(AOp, Wo, bo, y, meanp, rstdp, gnw, gnb);
}